// round 8
// baseline (speedup 1.0000x reference)
#include <cuda_runtime.h>
#include <cuda_bf16.h>
#include <cstdint>

#define T 48
#define E 32
#define C0 64
#define C1 64
#define H1 256
#define H2 128
#define NPRED 12
#define SEQS (16 * 2048)

__device__ float g_last[SEQS * C1];

// ---- kernel A smem byte offsets ----
#define O_WIN_H 0        // WinT [64n][40k] bf16 (k<32 valid), stride 80B
#define O_WIN_L 5120
#define O_WC_H  10240    // WcT 3 x [64n][72k] bf16, stride 144B, dt stride 9216
#define O_WC_L  37888
#define O_WKF   65536    // Wk fp32 [64][65]
#define O_WVF   82176    // Wv fp32 [64][65]
#define O_WQ    98816    // Wq fp32 [64][64]
#define O_X_H   115200   // x [96r][40k] bf16, stride 80B
#define O_X_L   122880
#define O_H_H   130560   // h padded [2][50][72] bf16, row stride 144B, seq stride 7200
#define O_H_L   144960
#define O_HC    159360   // hc fp32 [96][65]
#define O_LAST  184320   // fp32 [2][64]
#define O_SQ    184832   // fp32 [2][64]
#define O_QK    185344   // fp32 [2][64]
#define O_SC    185856   // fp32 [96] raw score dots
#define O_ATTN  186240   // fp32 [2][48]
#define O_R     186624   // fp32 [2][64]
#define O_BIAS  187136   // fp32: bin@0 bc@64 bk@128 bv@192 bq@256
#define SMEM_A  188416

// ---------------- warp MMA helpers (portable PTX, plain sm_103 OK) ----------------
__device__ __forceinline__ uint32_t smem_u32(const void* p) {
    uint32_t a;
    asm("{ .reg .u64 t; cvta.to.shared.u64 t, %1; cvt.u32.u64 %0, t; }" : "=r"(a) : "l"(p));
    return a;
}
__device__ __forceinline__ void hmma(float* d, const uint32_t* a, const uint32_t* b) {
    asm volatile(
        "mma.sync.aligned.m16n8k16.row.col.f32.bf16.bf16.f32 "
        "{%0,%1,%2,%3}, {%4,%5,%6,%7}, {%8,%9}, {%0,%1,%2,%3};"
        : "+f"(d[0]), "+f"(d[1]), "+f"(d[2]), "+f"(d[3])
        : "r"(a[0]), "r"(a[1]), "r"(a[2]), "r"(a[3]), "r"(b[0]), "r"(b[1]));
}
__device__ __forceinline__ void ldA(uint32_t* f, uint32_t rowbase, int stride, int k0, int lane) {
    int g = lane >> 3;
    uint32_t addr = rowbase + (uint32_t)(((lane & 7) + ((g & 1) << 3)) * stride
                                         + (k0 + ((g >> 1) << 3)) * 2);
    asm volatile("ldmatrix.sync.aligned.m8n8.x4.shared.b16 {%0,%1,%2,%3}, [%4];"
                 : "=r"(f[0]), "=r"(f[1]), "=r"(f[2]), "=r"(f[3]) : "r"(addr));
}
__device__ __forceinline__ void ldB(uint32_t* f, uint32_t base, int stride, int cb, int k0, int lane) {
    uint32_t addr = base + (uint32_t)((cb + (lane & 7)) * stride + k0 * 2
                                      + (((lane >> 3) & 1) << 4));
    asm volatile("ldmatrix.sync.aligned.m8n8.x2.shared.b16 {%0,%1}, [%2];"
                 : "=r"(f[0]), "=r"(f[1]) : "r"(addr));
}
__device__ __forceinline__ void splitw(float a, float b, uint32_t& hw, uint32_t& lw) {
    __nv_bfloat162 H = __floats2bfloat162_rn(a, b);
    float2 F = __bfloat1622float2(H);
    __nv_bfloat162 L = __floats2bfloat162_rn(a - F.x, b - F.y);
    hw = *reinterpret_cast<uint32_t*>(&H);
    lw = *reinterpret_cast<uint32_t*>(&L);
}

// ---------------- Kernel A ----------------
__global__ void __launch_bounds__(256, 1)
kernelA(const float* __restrict__ x,
        const float* __restrict__ Win, const float* __restrict__ bin,
        const float* __restrict__ Wc,  const float* __restrict__ bc,
        const float* __restrict__ Wq,  const float* __restrict__ bq,
        const float* __restrict__ Wk,  const float* __restrict__ bk,
        const float* __restrict__ Wv,  const float* __restrict__ bv)
{
    extern __shared__ char smc[];
    const uint32_t smb = smem_u32(smc);
    const int tid  = threadIdx.x;
    const int wid  = tid >> 5;
    const int lane = tid & 31;
    const int cb   = wid * 8;

    float* sBias = (float*)(smc + O_BIAS);
    float* sLast = (float*)(smc + O_LAST);
    float* sQ    = (float*)(smc + O_SQ);
    float* sQK   = (float*)(smc + O_QK);
    float* sSC   = (float*)(smc + O_SC);
    float* sAttn = (float*)(smc + O_ATTN);
    float* sR    = (float*)(smc + O_R);
    float* sHC   = (float*)(smc + O_HC);
    float* sWkF  = (float*)(smc + O_WKF);
    float* sWvF  = (float*)(smc + O_WVF);
    float* sWqF  = (float*)(smc + O_WQ);

    // ---- stage weights ----
    for (int i = tid; i < 2048; i += 256) {          // Win[e][c] -> WinT[c][e], split bf16
        int e = i >> 6, c = i & 63;
        float w = Win[i];
        __nv_bfloat16 h = __float2bfloat16(w);
        *(__nv_bfloat16*)(smc + O_WIN_H + c * 80 + e * 2) = h;
        *(__nv_bfloat16*)(smc + O_WIN_L + c * 80 + e * 2) =
            __float2bfloat16(w - __bfloat162float(h));
    }
    for (int i = tid; i < 12288; i += 256) {         // Wc[dt][ci][co] -> [dt][co][ci], split
        int dt = i >> 12, r = i & 4095, ci = r >> 6, co = r & 63;
        float w = Wc[i];
        __nv_bfloat16 h = __float2bfloat16(w);
        uint32_t o = dt * 9216 + co * 144 + ci * 2;
        *(__nv_bfloat16*)(smc + O_WC_H + o) = h;
        *(__nv_bfloat16*)(smc + O_WC_L + o) = __float2bfloat16(w - __bfloat162float(h));
    }
    for (int i = tid; i < 4096; i += 256) {          // Wk/Wv/Wq fp32 (exact paths)
        int ci = i >> 6, co = i & 63;
        sWkF[ci * 65 + co] = Wk[i];
        sWvF[ci * 65 + co] = Wv[i];
        sWqF[i] = Wq[i];
    }
    if (tid < 64) {
        sBias[tid]       = bin[tid];
        sBias[64 + tid]  = bc[tid];
        sBias[128 + tid] = bk[tid];
        sBias[192 + tid] = bv[tid];
        sBias[256 + tid] = bq[tid];
    }
    for (int i = tid; i < 7200; i += 256) ((uint32_t*)(smc + O_H_H))[i] = 0;
    __syncthreads();

    // ---- prologue: stage x for first pair ----
    {
        const float4* xg = (const float4*)(x + (size_t)(blockIdx.x * 2) * (T * E));
        #pragma unroll
        for (int kk = 0; kk < 3; kk++) {
            int idx = tid + kk * 256;
            float4 v = xg[idx];
            int row = idx >> 3, e4 = idx & 7;
            uint32_t o = (uint32_t)(row * 80 + e4 * 8);
            uint32_t h0, l0, h1, l1;
            splitw(v.x, v.y, h0, l0);
            splitw(v.z, v.w, h1, l1);
            *(uint32_t*)(smc + O_X_H + o)     = h0;
            *(uint32_t*)(smc + O_X_H + o + 4) = h1;
            *(uint32_t*)(smc + O_X_L + o)     = l0;
            *(uint32_t*)(smc + O_X_L + o + 4) = l1;
        }
    }
    __syncthreads();

    for (int pair = blockIdx.x; pair < SEQS / 2; pair += gridDim.x) {
        const int seq0 = pair * 2;

        // ---- GEMM1: h = x @ Win (K=32, split bf16 x3) ----
        {
            float acc[6][4] = {};
            #pragma unroll
            for (int k = 0; k < 2; k++) {
                int k0 = k * 16;
                uint32_t bh[2], bl[2];
                ldB(bh, smb + O_WIN_H, 80, cb, k0, lane);
                ldB(bl, smb + O_WIN_L, 80, cb, k0, lane);
                #pragma unroll
                for (int mt = 0; mt < 6; mt++) {
                    uint32_t ah[4], al[4];
                    ldA(ah, smb + O_X_H + mt * 16 * 80, 80, k0, lane);
                    ldA(al, smb + O_X_L + mt * 16 * 80, 80, k0, lane);
                    hmma(acc[mt], ah, bh);
                    hmma(acc[mt], ah, bl);
                    hmma(acc[mt], al, bh);
                }
            }
            int c = cb + (lane & 3) * 2;
            float b0 = sBias[c], b1 = sBias[c + 1];
            #pragma unroll
            for (int mt = 0; mt < 6; mt++) {
                int g0 = mt * 16 + (lane >> 2), g1 = g0 + 8;
                uint32_t h0, l0, h1, l1;
                splitw(acc[mt][0] + b0, acc[mt][1] + b1, h0, l0);
                splitw(acc[mt][2] + b0, acc[mt][3] + b1, h1, l1);
                int s0 = g0 / 48, t0 = g0 % 48;
                int s1 = g1 / 48, t1 = g1 % 48;
                uint32_t o0 = (uint32_t)(s0 * 7200 + (t0 + 1) * 144 + c * 2);
                uint32_t o1 = (uint32_t)(s1 * 7200 + (t1 + 1) * 144 + c * 2);
                *(uint32_t*)(smc + O_H_H + o0) = h0;
                *(uint32_t*)(smc + O_H_L + o0) = l0;
                *(uint32_t*)(smc + O_H_H + o1) = h1;
                *(uint32_t*)(smc + O_H_L + o1) = l1;
            }
        }
        __syncthreads();

        // ---- prefetch next pair's x (latency hidden under conv GEMM) ----
        const int npair = pair + gridDim.x;
        const bool hasnext = npair < SEQS / 2;
        float4 nx0, nx1, nx2;
        if (hasnext) {
            const float4* xg = (const float4*)(x + (size_t)(npair * 2) * (T * E));
            nx0 = xg[tid];
            nx1 = xg[tid + 256];
            nx2 = xg[tid + 512];
        }

        // ---- GEMM2: hc = relu(conv(h) + bc), store fp32 [96][65] ----
        {
            float acc[6][4] = {};
            #pragma unroll
            for (int dt = 0; dt < 3; dt++) {
                #pragma unroll
                for (int k = 0; k < 4; k++) {
                    int k0 = k * 16;
                    uint32_t bh[2], bl[2];
                    ldB(bh, smb + O_WC_H + dt * 9216, 144, cb, k0, lane);
                    ldB(bl, smb + O_WC_L + dt * 9216, 144, cb, k0, lane);
                    #pragma unroll
                    for (int mt = 0; mt < 6; mt++) {
                        int sq = (mt >= 3), t0 = (mt - sq * 3) * 16;
                        uint32_t rb = (uint32_t)(sq * 7200 + (t0 + dt) * 144);
                        uint32_t ah[4], al[4];
                        ldA(ah, smb + O_H_H + rb, 144, k0, lane);
                        ldA(al, smb + O_H_L + rb, 144, k0, lane);
                        hmma(acc[mt], ah, bh);
                        hmma(acc[mt], ah, bl);
                        hmma(acc[mt], al, bh);
                    }
                }
            }
            int c = cb + (lane & 3) * 2;
            float b0 = sBias[64 + c], b1 = sBias[64 + c + 1];
            #pragma unroll
            for (int mt = 0; mt < 6; mt++) {
                int g0 = mt * 16 + (lane >> 2), g1 = g0 + 8;
                float v0 = fmaxf(acc[mt][0] + b0, 0.f), v1 = fmaxf(acc[mt][1] + b1, 0.f);
                float v2 = fmaxf(acc[mt][2] + b0, 0.f), v3 = fmaxf(acc[mt][3] + b1, 0.f);
                sHC[g0 * 65 + c]     = v0;
                sHC[g0 * 65 + c + 1] = v1;
                sHC[g1 * 65 + c]     = v2;
                sHC[g1 * 65 + c + 1] = v3;
                if ((g1 % 48) == 47) {
                    int s = g1 / 48;
                    sLast[s * 64 + c]     = v2;
                    sLast[s * 64 + c + 1] = v3;
                }
            }
        }
        __syncthreads();

        // ---- q = bq + hc_last @ Wq (exact fp32, 256 threads) ----
        {
            int s  = tid >> 7;
            int c  = (tid >> 1) & 63;
            int hh = tid & 1;
            const float* hl = sLast + s * 64;
            float a = hh ? 0.f : sBias[256 + c];
            int base = hh * 32;
            #pragma unroll 8
            for (int ci = 0; ci < 32; ci++) a += hl[base + ci] * sWqF[(base + ci) * 64 + c];
            a += __shfl_xor_sync(0xffffffffu, a, 1);
            if (!hh) sQ[s * 64 + c] = a;
        }
        __syncthreads();

        // ---- qk = Wk @ q (exact fp32) ----
        if (tid < 128) {
            int s = tid >> 6, ci = tid & 63;
            const float* q = sQ + s * 64;
            const float* wr = sWkF + ci * 65;
            float a = 0.f;
            #pragma unroll 8
            for (int co = 0; co < 64; co++) a += q[co] * wr[co];
            sQK[s * 64 + ci] = a;
        }
        __syncthreads();

        // ---- raw scores: sc[t] = <qk, hc[t]> ----
        if (tid < 192) {
            int row = tid >> 1, hh = tid & 1;
            int s = row >= 48;
            const float* qk = sQK + s * 64 + hh * 32;
            const float* hr = sHC + row * 65 + hh * 32;
            float p = 0.f;
            #pragma unroll 8
            for (int j = 0; j < 32; j++) p += qk[j] * hr[j];
            p += __shfl_xor_sync(0xffffffffu, p, 1);
            if (!hh) sSC[row] = p;
        }
        __syncthreads();

        // ---- softmax over 48 (warp s); logits = (sc + q.bk)/8 ----
        if (wid < 2) {
            const float* q = sQ + wid * 64;
            const float* kb = sBias + 128;
            float qb = q[lane] * kb[lane] + q[lane + 32] * kb[lane + 32];
            #pragma unroll
            for (int o = 16; o > 0; o >>= 1) qb += __shfl_xor_sync(0xffffffffu, qb, o);
            int base = wid * 48;
            float a  = (sSC[base + lane] + qb) * 0.125f;
            float b2 = (lane < 16) ? (sSC[base + 32 + lane] + qb) * 0.125f : -1e30f;
            float m = fmaxf(a, b2);
            #pragma unroll
            for (int o = 16; o > 0; o >>= 1) m = fmaxf(m, __shfl_xor_sync(0xffffffffu, m, o));
            float ea = __expf(a - m);
            float eb = (lane < 16) ? __expf(b2 - m) : 0.f;
            float sden = ea + eb;
            #pragma unroll
            for (int o = 16; o > 0; o >>= 1) sden += __shfl_xor_sync(0xffffffffu, sden, o);
            float inv = 1.f / sden;
            sAttn[wid * 48 + lane] = ea * inv;
            if (lane < 16) sAttn[wid * 48 + 32 + lane] = eb * inv;
        }
        __syncthreads();

        // ---- r = attn^T . hc ----
        if (tid < 128) {
            int s = tid >> 6, c = tid & 63;
            const float* at = sAttn + s * 48;
            const float* hb = sHC + s * 48 * 65 + c;
            float a = 0.f;
            #pragma unroll
            for (int t = 0; t < 48; t++) a += at[t] * hb[t * 65];
            sR[s * 64 + c] = a;
        }
        __syncthreads();

        // ---- ctx = r @ Wv + bv -> g_last ----
        if (tid < 128) {
            int s = tid >> 6, co = tid & 63;
            const float* r = sR + s * 64;
            float a = sBias[192 + co];
            #pragma unroll 8
            for (int ci = 0; ci < 64; ci++) a += r[ci] * sWvF[ci * 65 + co];
            g_last[(size_t)(seq0 + s) * 64 + co] = a;
        }

        // ---- store prefetched x for next iteration ----
        if (hasnext) {
            #pragma unroll
            for (int kk = 0; kk < 3; kk++) {
                float4 v = (kk == 0) ? nx0 : (kk == 1) ? nx1 : nx2;
                int idx = tid + kk * 256;
                int row = idx >> 3, e4 = idx & 7;
                uint32_t o = (uint32_t)(row * 80 + e4 * 8);
                uint32_t h0, l0, h1, l1;
                splitw(v.x, v.y, h0, l0);
                splitw(v.z, v.w, h1, l1);
                *(uint32_t*)(smc + O_X_H + o)     = h0;
                *(uint32_t*)(smc + O_X_H + o + 4) = h1;
                *(uint32_t*)(smc + O_X_L + o)     = l0;
                *(uint32_t*)(smc + O_X_L + o + 4) = l1;
            }
        }
        __syncthreads();
    }
}

// ---------------- Kernel B: MLP with weight-reuse tiling (16 rows/iter) ----------------
#define SMEM_B_FLOATS 56880

__global__ void __launch_bounds__(256, 1)
kernelB(const float* __restrict__ W1, const float* __restrict__ b1,
        const float* __restrict__ W2, const float* __restrict__ b2,
        const float* __restrict__ W3, const float* __restrict__ b3,
        float* __restrict__ out)
{
    extern __shared__ float sm[];
    float* sW1 = sm;
    float* sW2 = sm + 16384;
    float* sb1 = sm + 49152;
    float* sb2 = sm + 49408;
    float* sb3 = sm + 49536;
    float* sIn = sm + 49552;   // [16][65]
    float* sZ1 = sm + 50592;   // [16][261]
    float* sZ2 = sm + 54768;   // [16][132]

    const int tid  = threadIdx.x;
    const int wid  = tid >> 5;
    const int lane = tid & 31;

    for (int i = tid; i < 16384; i += 256) sW1[i] = W1[i];
    for (int i = tid; i < 32768; i += 256) sW2[i] = W2[i];
    if (tid < 256) sb1[tid] = b1[tid];
    if (tid < 128) sb2[tid] = b2[tid];
    if (tid < 12)  sb3[tid] = b3[tid];
    __syncthreads();

    const int l1_c4 = lane & 7;
    const int l1_r  = lane >> 3;
    const int l1_cb = wid * 32;
    const int l2_c4 = lane & 3;
    const int l2_r  = lane >> 2;
    const int l2_cb = wid * 16;

    for (int base = blockIdx.x * 16; base < SEQS; base += gridDim.x * 16) {
        {
            float4 v = ((const float4*)(g_last + (size_t)base * C1))[tid];
            int row = tid >> 4, e4 = tid & 15;
            float* d = sIn + row * 65 + e4 * 4;
            d[0] = v.x; d[1] = v.y; d[2] = v.z; d[3] = v.w;
        }
        __syncthreads();

        {
            float4 bb = ((const float4*)(sb1 + l1_cb))[l1_c4];
            float acc[4][4];
            #pragma unroll
            for (int j = 0; j < 4; j++) {
                acc[j][0] = bb.x; acc[j][1] = bb.y; acc[j][2] = bb.z; acc[j][3] = bb.w;
            }
            #pragma unroll 8
            for (int f = 0; f < 64; f++) {
                float4 w = ((const float4*)(sW1 + f * H1 + l1_cb))[l1_c4];
                float a0 = sIn[l1_r * 65 + f];
                float a1 = sIn[(l1_r + 4) * 65 + f];
                float a2 = sIn[(l1_r + 8) * 65 + f];
                float a3 = sIn[(l1_r + 12) * 65 + f];
                acc[0][0] += a0 * w.x; acc[0][1] += a0 * w.y; acc[0][2] += a0 * w.z; acc[0][3] += a0 * w.w;
                acc[1][0] += a1 * w.x; acc[1][1] += a1 * w.y; acc[1][2] += a1 * w.z; acc[1][3] += a1 * w.w;
                acc[2][0] += a2 * w.x; acc[2][1] += a2 * w.y; acc[2][2] += a2 * w.z; acc[2][3] += a2 * w.w;
                acc[3][0] += a3 * w.x; acc[3][1] += a3 * w.y; acc[3][2] += a3 * w.z; acc[3][3] += a3 * w.w;
            }
            #pragma unroll
            for (int j = 0; j < 4; j++) {
                float* d = sZ1 + (l1_r + 4 * j) * 261 + l1_cb + l1_c4 * 4;
                d[0] = fmaxf(acc[j][0], 0.f);
                d[1] = fmaxf(acc[j][1], 0.f);
                d[2] = fmaxf(acc[j][2], 0.f);
                d[3] = fmaxf(acc[j][3], 0.f);
            }
        }
        __syncthreads();

        {
            float4 bb = ((const float4*)(sb2 + l2_cb))[l2_c4];
            float a0[4] = {bb.x, bb.y, bb.z, bb.w};
            float a1[4] = {bb.x, bb.y, bb.z, bb.w};
            #pragma unroll 8
            for (int f = 0; f < 256; f++) {
                float4 w = ((const float4*)(sW2 + f * H2 + l2_cb))[l2_c4];
                float z0 = sZ1[l2_r * 261 + f];
                float z1 = sZ1[(l2_r + 8) * 261 + f];
                a0[0] += z0 * w.x; a0[1] += z0 * w.y; a0[2] += z0 * w.z; a0[3] += z0 * w.w;
                a1[0] += z1 * w.x; a1[1] += z1 * w.y; a1[2] += z1 * w.z; a1[3] += z1 * w.w;
            }
            ((float4*)(sZ2 + l2_r * 132 + l2_cb))[l2_c4] =
                make_float4(fmaxf(a0[0], 0.f), fmaxf(a0[1], 0.f), fmaxf(a0[2], 0.f), fmaxf(a0[3], 0.f));
            ((float4*)(sZ2 + (l2_r + 8) * 132 + l2_cb))[l2_c4] =
                make_float4(fmaxf(a1[0], 0.f), fmaxf(a1[1], 0.f), fmaxf(a1[2], 0.f), fmaxf(a1[3], 0.f));
        }
        __syncthreads();

        if (tid < 192) {
            int r = tid / 12, p = tid % 12;
            const float* zr = sZ2 + r * 132;
            float a = sb3[p];
            #pragma unroll 16
            for (int f = 0; f < 128; f++) a += zr[f] * __ldg(&W3[f * NPRED + p]);
            int seqr = base + r;
            int bb = seqr >> 11;
            int nn = seqr & 2047;
            out[(size_t)bb * (NPRED * 2048) + p * 2048 + nn] = a;
        }
        __syncthreads();
    }
}

extern "C" void kernel_launch(void* const* d_in, const int* in_sizes, int n_in,
                              void* d_out, int out_size)
{
    const float* x     = (const float*)d_in[0];
    const float* W_in  = (const float*)d_in[1];
    const float* b_in  = (const float*)d_in[2];
    const float* W_c   = (const float*)d_in[3];
    const float* b_c   = (const float*)d_in[4];
    const float* Wq    = (const float*)d_in[5];
    const float* bq    = (const float*)d_in[6];
    const float* Wk    = (const float*)d_in[7];
    const float* bk    = (const float*)d_in[8];
    const float* Wv    = (const float*)d_in[9];
    const float* bv    = (const float*)d_in[10];
    const float* W1    = (const float*)d_in[11];
    const float* b1    = (const float*)d_in[12];
    const float* W2    = (const float*)d_in[13];
    const float* b2    = (const float*)d_in[14];
    const float* W3    = (const float*)d_in[15];
    const float* b3    = (const float*)d_in[16];

    size_t smemB = SMEM_B_FLOATS * sizeof(float);
    cudaFuncSetAttribute(kernelA, cudaFuncAttributeMaxDynamicSharedMemorySize, SMEM_A);
    cudaFuncSetAttribute(kernelB, cudaFuncAttributeMaxDynamicSharedMemorySize, (int)smemB);

    kernelA<<<152, 256, SMEM_A>>>(x, W_in, b_in, W_c, b_c, Wq, bq, Wk, bk, Wv, bv);
    kernelB<<<152, 256, smemB>>>(W1, b1, W2, b2, W3, b3, (float*)d_out);
}

// round 9
// speedup vs baseline: 1.3524x; 1.3524x over previous
#include <cuda_runtime.h>
#include <cuda_bf16.h>
#include <cstdint>

#define T 48
#define E 32
#define C0 64
#define C1 64
#define H1 256
#define H2 128
#define NPRED 12
#define SEQS (16 * 2048)

__device__ float g_last[SEQS * C1];

// ---- kernel A smem byte offsets ----
#define O_WIN_H 0        // WinT [64n][40k] bf16, stride 80B
#define O_WIN_L 5120
#define O_WC_H  10240    // WcT 3 x [64n][72k] bf16, stride 144B, dt stride 9216
#define O_WC_L  37888
#define O_M     65536    // M = Wq.Wk^T fp32 [64j][65ci]
#define O_WVF   82176    // Wv fp32 [64][65]
#define O_X_H   98816    // x [96r][40k] bf16, stride 80B
#define O_X_L   106496
#define O_H_H   114176   // h padded [2][50][72] bf16, row stride 144B, seq stride 7200
#define O_H_L   128576
#define O_HC    142976   // hc fp32 [96][65]
#define O_LAST  167936   // fp32 [2][64]
#define O_QK    168448   // fp32 [2][64]
#define O_SC    168960   // fp32 [96]
#define O_ATTN  169344   // fp32 [2][48]
#define O_R     169728   // fp32 [2][64]
#define O_QB    170240   // fp32 [2]
#define O_C0    170248   // fp32 [1] (+pad)
#define O_WKBQ  170256   // fp32 [64]
#define O_WQBK  170512   // fp32 [64]
#define O_BIAS  170768   // fp32: bin@0 bc@64 bv@128
#define SMEM_A  171536

// ---------------- warp MMA helpers (portable PTX, plain sm_103 OK) ----------------
__device__ __forceinline__ uint32_t smem_u32(const void* p) {
    uint32_t a;
    asm("{ .reg .u64 t; cvta.to.shared.u64 t, %1; cvt.u32.u64 %0, t; }" : "=r"(a) : "l"(p));
    return a;
}
__device__ __forceinline__ void hmma(float* d, const uint32_t* a, const uint32_t* b) {
    asm volatile(
        "mma.sync.aligned.m16n8k16.row.col.f32.bf16.bf16.f32 "
        "{%0,%1,%2,%3}, {%4,%5,%6,%7}, {%8,%9}, {%0,%1,%2,%3};"
        : "+f"(d[0]), "+f"(d[1]), "+f"(d[2]), "+f"(d[3])
        : "r"(a[0]), "r"(a[1]), "r"(a[2]), "r"(a[3]), "r"(b[0]), "r"(b[1]));
}
__device__ __forceinline__ void ldA(uint32_t* f, uint32_t rowbase, int stride, int k0, int lane) {
    int g = lane >> 3;
    uint32_t addr = rowbase + (uint32_t)(((lane & 7) + ((g & 1) << 3)) * stride
                                         + (k0 + ((g >> 1) << 3)) * 2);
    asm volatile("ldmatrix.sync.aligned.m8n8.x4.shared.b16 {%0,%1,%2,%3}, [%4];"
                 : "=r"(f[0]), "=r"(f[1]), "=r"(f[2]), "=r"(f[3]) : "r"(addr));
}
__device__ __forceinline__ void ldB(uint32_t* f, uint32_t base, int stride, int cb, int k0, int lane) {
    uint32_t addr = base + (uint32_t)((cb + (lane & 7)) * stride + k0 * 2
                                      + (((lane >> 3) & 1) << 4));
    asm volatile("ldmatrix.sync.aligned.m8n8.x2.shared.b16 {%0,%1}, [%2];"
                 : "=r"(f[0]), "=r"(f[1]) : "r"(addr));
}
__device__ __forceinline__ void splitw(float a, float b, uint32_t& hw, uint32_t& lw) {
    __nv_bfloat162 H = __floats2bfloat162_rn(a, b);
    float2 F = __bfloat1622float2(H);
    __nv_bfloat162 L = __floats2bfloat162_rn(a - F.x, b - F.y);
    hw = *reinterpret_cast<uint32_t*>(&H);
    lw = *reinterpret_cast<uint32_t*>(&L);
}

// ---------------- Kernel A: 512 threads, 16 warps, folded attention algebra ----------------
__global__ void __launch_bounds__(512, 1)
kernelA(const float* __restrict__ x,
        const float* __restrict__ Win, const float* __restrict__ bin,
        const float* __restrict__ Wc,  const float* __restrict__ bc,
        const float* __restrict__ Wq,  const float* __restrict__ bq,
        const float* __restrict__ Wk,  const float* __restrict__ bk,
        const float* __restrict__ Wv,  const float* __restrict__ bv)
{
    extern __shared__ char smc[];
    const uint32_t smb = smem_u32(smc);
    const int tid  = threadIdx.x;
    const int wid  = tid >> 5;
    const int lane = tid & 31;
    const int cbase = (wid & 7) * 8;     // warp's output col base
    const int mts   = (wid >> 3) * 3;    // warp's first M-tile (0 or 3)

    float* sBias = (float*)(smc + O_BIAS);
    float* sLast = (float*)(smc + O_LAST);
    float* sQK   = (float*)(smc + O_QK);
    float* sSC   = (float*)(smc + O_SC);
    float* sAttn = (float*)(smc + O_ATTN);
    float* sR    = (float*)(smc + O_R);
    float* sQB   = (float*)(smc + O_QB);
    float* sC0   = (float*)(smc + O_C0);
    float* sWKBQ = (float*)(smc + O_WKBQ);
    float* sWQBK = (float*)(smc + O_WQBK);
    float* sHC   = (float*)(smc + O_HC);
    float* sM    = (float*)(smc + O_M);
    float* sWvF  = (float*)(smc + O_WVF);

    // ---- stage weights ----
    for (int i = tid; i < 2048; i += 512) {
        int e = i >> 6, c = i & 63;
        float w = Win[i];
        __nv_bfloat16 h = __float2bfloat16(w);
        *(__nv_bfloat16*)(smc + O_WIN_H + c * 80 + e * 2) = h;
        *(__nv_bfloat16*)(smc + O_WIN_L + c * 80 + e * 2) =
            __float2bfloat16(w - __bfloat162float(h));
    }
    for (int i = tid; i < 12288; i += 512) {
        int dt = i >> 12, r = i & 4095, ci = r >> 6, co = r & 63;
        float w = Wc[i];
        __nv_bfloat16 h = __float2bfloat16(w);
        uint32_t o = dt * 9216 + co * 144 + ci * 2;
        *(__nv_bfloat16*)(smc + O_WC_H + o) = h;
        *(__nv_bfloat16*)(smc + O_WC_L + o) = __float2bfloat16(w - __bfloat162float(h));
    }
    // M = Wq . Wk^T (exact fp32, one-time)
    for (int i = tid; i < 4096; i += 512) {
        int j = i >> 6, ci = i & 63;
        float a = 0.f;
        #pragma unroll 8
        for (int co = 0; co < 64; co++) a += Wq[j * 64 + co] * Wk[ci * 64 + co];
        sM[j * 65 + ci] = a;
    }
    // Wv fp32 [ci][co] padded
    for (int i = tid; i < 4096; i += 512) {
        int ci = i >> 6, co = i & 63;
        sWvF[ci * 65 + co] = Wv[i];
    }
    if (tid < 64) {
        float a = 0.f;
        #pragma unroll 8
        for (int co = 0; co < 64; co++) a += Wk[tid * 64 + co] * bq[co];
        sWKBQ[tid] = a;
        float b2 = 0.f;
        #pragma unroll 8
        for (int co = 0; co < 64; co++) b2 += Wq[tid * 64 + co] * bk[co];
        sWQBK[tid] = b2;
        sBias[tid]       = bin[tid];
        sBias[64 + tid]  = bc[tid];
        sBias[128 + tid] = bv[tid];
    }
    if (tid == 0) {
        float c = 0.f;
        #pragma unroll 8
        for (int co = 0; co < 64; co++) c += bq[co] * bk[co];
        sC0[0] = c;
    }
    for (int i = tid; i < 7200; i += 512) ((uint32_t*)(smc + O_H_H))[i] = 0;
    __syncthreads();

    // ---- prologue: stage x for first pair ----
    {
        const float4* xg = (const float4*)(x + (size_t)(blockIdx.x * 2) * (T * E));
        for (int idx = tid; idx < 768; idx += 512) {
            float4 v = xg[idx];
            int row = idx >> 3, e4 = idx & 7;
            uint32_t o = (uint32_t)(row * 80 + e4 * 8);
            uint32_t h0, l0, h1, l1;
            splitw(v.x, v.y, h0, l0);
            splitw(v.z, v.w, h1, l1);
            *(uint32_t*)(smc + O_X_H + o)     = h0;
            *(uint32_t*)(smc + O_X_H + o + 4) = h1;
            *(uint32_t*)(smc + O_X_L + o)     = l0;
            *(uint32_t*)(smc + O_X_L + o + 4) = l1;
        }
    }
    __syncthreads();

    for (int pair = blockIdx.x; pair < SEQS / 2; pair += gridDim.x) {
        const int seq0 = pair * 2;

        // ---- GEMM1: h = x @ Win (K=32, 3 M-tiles per warp) ----
        {
            float acc[3][4] = {};
            #pragma unroll
            for (int k = 0; k < 2; k++) {
                int k0 = k * 16;
                uint32_t bh[2], bl[2];
                ldB(bh, smb + O_WIN_H, 80, cbase, k0, lane);
                ldB(bl, smb + O_WIN_L, 80, cbase, k0, lane);
                #pragma unroll
                for (int j = 0; j < 3; j++) {
                    int mt = mts + j;
                    uint32_t ah[4], al[4];
                    ldA(ah, smb + O_X_H + mt * 16 * 80, 80, k0, lane);
                    ldA(al, smb + O_X_L + mt * 16 * 80, 80, k0, lane);
                    hmma(acc[j], ah, bh);
                    hmma(acc[j], ah, bl);
                    hmma(acc[j], al, bh);
                }
            }
            int c = cbase + (lane & 3) * 2;
            float b0 = sBias[c], b1 = sBias[c + 1];
            #pragma unroll
            for (int j = 0; j < 3; j++) {
                int mt = mts + j;
                int g0 = mt * 16 + (lane >> 2), g1 = g0 + 8;
                uint32_t h0, l0, h1, l1;
                splitw(acc[j][0] + b0, acc[j][1] + b1, h0, l0);
                splitw(acc[j][2] + b0, acc[j][3] + b1, h1, l1);
                int s0 = g0 / 48, t0 = g0 % 48;
                int s1 = g1 / 48, t1 = g1 % 48;
                uint32_t o0 = (uint32_t)(s0 * 7200 + (t0 + 1) * 144 + c * 2);
                uint32_t o1 = (uint32_t)(s1 * 7200 + (t1 + 1) * 144 + c * 2);
                *(uint32_t*)(smc + O_H_H + o0) = h0;
                *(uint32_t*)(smc + O_H_L + o0) = l0;
                *(uint32_t*)(smc + O_H_H + o1) = h1;
                *(uint32_t*)(smc + O_H_L + o1) = l1;
            }
        }
        __syncthreads();

        // ---- prefetch next pair's x ----
        const int npair = pair + gridDim.x;
        const bool hasnext = npair < SEQS / 2;
        float4 nx0, nx1;
        if (hasnext) {
            const float4* xg = (const float4*)(x + (size_t)(npair * 2) * (T * E));
            nx0 = xg[tid];
            if (tid < 256) nx1 = xg[tid + 512];
        }

        // ---- GEMM2: hc = relu(conv(h) + bc), fp32 [96][65] ----
        {
            float acc[3][4] = {};
            #pragma unroll
            for (int dt = 0; dt < 3; dt++) {
                #pragma unroll
                for (int k = 0; k < 4; k++) {
                    int k0 = k * 16;
                    uint32_t bh[2], bl[2];
                    ldB(bh, smb + O_WC_H + dt * 9216, 144, cbase, k0, lane);
                    ldB(bl, smb + O_WC_L + dt * 9216, 144, cbase, k0, lane);
                    #pragma unroll
                    for (int j = 0; j < 3; j++) {
                        int mt = mts + j;
                        int sq = (mt >= 3), t0 = (mt - sq * 3) * 16;
                        uint32_t rb = (uint32_t)(sq * 7200 + (t0 + dt) * 144);
                        uint32_t ah[4], al[4];
                        ldA(ah, smb + O_H_H + rb, 144, k0, lane);
                        ldA(al, smb + O_H_L + rb, 144, k0, lane);
                        hmma(acc[j], ah, bh);
                        hmma(acc[j], ah, bl);
                        hmma(acc[j], al, bh);
                    }
                }
            }
            int c = cbase + (lane & 3) * 2;
            float b0 = sBias[64 + c], b1 = sBias[64 + c + 1];
            #pragma unroll
            for (int j = 0; j < 3; j++) {
                int mt = mts + j;
                int g0 = mt * 16 + (lane >> 2), g1 = g0 + 8;
                float v0 = fmaxf(acc[j][0] + b0, 0.f), v1 = fmaxf(acc[j][1] + b1, 0.f);
                float v2 = fmaxf(acc[j][2] + b0, 0.f), v3 = fmaxf(acc[j][3] + b1, 0.f);
                sHC[g0 * 65 + c]     = v0;
                sHC[g0 * 65 + c + 1] = v1;
                sHC[g1 * 65 + c]     = v2;
                sHC[g1 * 65 + c + 1] = v3;
                if ((g1 % 48) == 47) {
                    int s = g1 / 48;
                    sLast[s * 64 + c]     = v2;
                    sLast[s * 64 + c + 1] = v3;
                }
            }
        }
        __syncthreads();

        // ---- qk = M^T hc_last + wkbq ; qb = <hc_last, wqbk> + c0 ----
        if (tid < 256) {
            int s = tid >> 7, i2 = (tid >> 1) & 63, hh = tid & 1;
            const float* hl = sLast + s * 64;
            float a = hh ? 0.f : sWKBQ[i2];
            int base = hh * 32;
            #pragma unroll 8
            for (int j = 0; j < 32; j++) a += hl[base + j] * sM[(base + j) * 65 + i2];
            a += __shfl_xor_sync(0xffffffffu, a, 1);
            if (!hh) sQK[s * 64 + i2] = a;
        } else if (tid < 320) {
            int s = (tid >> 5) & 1;          // warp 8 -> s=0, warp 9 -> s=1
            const float* hl = sLast + s * 64;
            float a = hl[lane] * sWQBK[lane] + hl[lane + 32] * sWQBK[lane + 32];
            #pragma unroll
            for (int o = 16; o > 0; o >>= 1) a += __shfl_xor_sync(0xffffffffu, a, o);
            if (lane == 0) sQB[s] = a + sC0[0];
        }
        __syncthreads();

        // ---- raw scores sc[t] = <qk, hc[t]> (384 threads, quad/row) ----
        if (tid < 384) {
            int row = tid >> 2, qq = tid & 3;
            int s = row >= 48;
            const float* qk = sQK + s * 64 + qq * 16;
            const float* hr = sHC + row * 65 + qq * 16;
            float p = 0.f;
            #pragma unroll
            for (int j = 0; j < 16; j++) p += qk[j] * hr[j];
            p += __shfl_xor_sync(0xffffffffu, p, 1);
            p += __shfl_xor_sync(0xffffffffu, p, 2);
            if (qq == 0) sSC[row] = p;
        }
        __syncthreads();

        // ---- softmax over 48 (warp s) ----
        if (wid < 2) {
            float qb = sQB[wid];
            int base = wid * 48;
            float a  = (sSC[base + lane] + qb) * 0.125f;
            float b2 = (lane < 16) ? (sSC[base + 32 + lane] + qb) * 0.125f : -1e30f;
            float m = fmaxf(a, b2);
            #pragma unroll
            for (int o = 16; o > 0; o >>= 1) m = fmaxf(m, __shfl_xor_sync(0xffffffffu, m, o));
            float ea = __expf(a - m);
            float eb = (lane < 16) ? __expf(b2 - m) : 0.f;
            float sden = ea + eb;
            #pragma unroll
            for (int o = 16; o > 0; o >>= 1) sden += __shfl_xor_sync(0xffffffffu, sden, o);
            float inv = 1.f / sden;
            sAttn[base + lane] = ea * inv;
            if (lane < 16) sAttn[base + 32 + lane] = eb * inv;
        }
        __syncthreads();

        // ---- r = attn^T . hc (256 threads, 24 MAC each) ----
        if (tid < 256) {
            int s = tid >> 7, c = (tid >> 1) & 63, hh = tid & 1;
            const float* at = sAttn + s * 48 + hh * 24;
            const float* hb = sHC + (s * 48 + hh * 24) * 65 + c;
            float a = 0.f;
            #pragma unroll
            for (int t = 0; t < 24; t++) a += at[t] * hb[t * 65];
            a += __shfl_xor_sync(0xffffffffu, a, 1);
            if (!hh) sR[s * 64 + c] = a;
        }
        __syncthreads();

        // ---- ctx = r @ Wv + bv -> g_last ; store prefetched x ----
        if (tid < 256) {
            int s = tid >> 7, co = (tid >> 1) & 63, hh = tid & 1;
            const float* r = sR + s * 64 + hh * 32;
            float a = hh ? 0.f : sBias[128 + co];
            #pragma unroll 8
            for (int ci = 0; ci < 32; ci++) a += r[ci] * sWvF[(hh * 32 + ci) * 65 + co];
            a += __shfl_xor_sync(0xffffffffu, a, 1);
            if (!hh) g_last[(size_t)(seq0 + s) * 64 + co] = a;
        }
        if (hasnext) {
            {
                float4 v = nx0;
                int row = tid >> 3, e4 = tid & 7;
                uint32_t o = (uint32_t)(row * 80 + e4 * 8);
                uint32_t h0, l0, h1, l1;
                splitw(v.x, v.y, h0, l0);
                splitw(v.z, v.w, h1, l1);
                *(uint32_t*)(smc + O_X_H + o)     = h0;
                *(uint32_t*)(smc + O_X_H + o + 4) = h1;
                *(uint32_t*)(smc + O_X_L + o)     = l0;
                *(uint32_t*)(smc + O_X_L + o + 4) = l1;
            }
            if (tid < 256) {
                float4 v = nx1;
                int idx = tid + 512;
                int row = idx >> 3, e4 = idx & 7;
                uint32_t o = (uint32_t)(row * 80 + e4 * 8);
                uint32_t h0, l0, h1, l1;
                splitw(v.x, v.y, h0, l0);
                splitw(v.z, v.w, h1, l1);
                *(uint32_t*)(smc + O_X_H + o)     = h0;
                *(uint32_t*)(smc + O_X_H + o + 4) = h1;
                *(uint32_t*)(smc + O_X_L + o)     = l0;
                *(uint32_t*)(smc + O_X_L + o + 4) = l1;
            }
        }
        __syncthreads();
    }
}

// ---------------- Kernel B: MLP (proven round-7 version, also clock canary) ----------------
#define SMEM_B_FLOATS 56880

__global__ void __launch_bounds__(256, 1)
kernelB(const float* __restrict__ W1, const float* __restrict__ b1,
        const float* __restrict__ W2, const float* __restrict__ b2,
        const float* __restrict__ W3, const float* __restrict__ b3,
        float* __restrict__ out)
{
    extern __shared__ float sm[];
    float* sW1 = sm;
    float* sW2 = sm + 16384;
    float* sb1 = sm + 49152;
    float* sb2 = sm + 49408;
    float* sb3 = sm + 49536;
    float* sIn = sm + 49552;   // [16][65]
    float* sZ1 = sm + 50592;   // [16][261]
    float* sZ2 = sm + 54768;   // [16][132]

    const int tid  = threadIdx.x;
    const int wid  = tid >> 5;
    const int lane = tid & 31;

    for (int i = tid; i < 16384; i += 256) sW1[i] = W1[i];
    for (int i = tid; i < 32768; i += 256) sW2[i] = W2[i];
    if (tid < 256) sb1[tid] = b1[tid];
    if (tid < 128) sb2[tid] = b2[tid];
    if (tid < 12)  sb3[tid] = b3[tid];
    __syncthreads();

    const int l1_c4 = lane & 7;
    const int l1_r  = lane >> 3;
    const int l1_cb = wid * 32;
    const int l2_c4 = lane & 3;
    const int l2_r  = lane >> 2;
    const int l2_cb = wid * 16;

    for (int base = blockIdx.x * 16; base < SEQS; base += gridDim.x * 16) {
        {
            float4 v = ((const float4*)(g_last + (size_t)base * C1))[tid];
            int row = tid >> 4, e4 = tid & 15;
            float* d = sIn + row * 65 + e4 * 4;
            d[0] = v.x; d[1] = v.y; d[2] = v.z; d[3] = v.w;
        }
        __syncthreads();

        {
            float4 bb = ((const float4*)(sb1 + l1_cb))[l1_c4];
            float acc[4][4];
            #pragma unroll
            for (int j = 0; j < 4; j++) {
                acc[j][0] = bb.x; acc[j][1] = bb.y; acc[j][2] = bb.z; acc[j][3] = bb.w;
            }
            #pragma unroll 8
            for (int f = 0; f < 64; f++) {
                float4 w = ((const float4*)(sW1 + f * H1 + l1_cb))[l1_c4];
                float a0 = sIn[l1_r * 65 + f];
                float a1 = sIn[(l1_r + 4) * 65 + f];
                float a2 = sIn[(l1_r + 8) * 65 + f];
                float a3 = sIn[(l1_r + 12) * 65 + f];
                acc[0][0] += a0 * w.x; acc[0][1] += a0 * w.y; acc[0][2] += a0 * w.z; acc[0][3] += a0 * w.w;
                acc[1][0] += a1 * w.x; acc[1][1] += a1 * w.y; acc[1][2] += a1 * w.z; acc[1][3] += a1 * w.w;
                acc[2][0] += a2 * w.x; acc[2][1] += a2 * w.y; acc[2][2] += a2 * w.z; acc[2][3] += a2 * w.w;
                acc[3][0] += a3 * w.x; acc[3][1] += a3 * w.y; acc[3][2] += a3 * w.z; acc[3][3] += a3 * w.w;
            }
            #pragma unroll
            for (int j = 0; j < 4; j++) {
                float* d = sZ1 + (l1_r + 4 * j) * 261 + l1_cb + l1_c4 * 4;
                d[0] = fmaxf(acc[j][0], 0.f);
                d[1] = fmaxf(acc[j][1], 0.f);
                d[2] = fmaxf(acc[j][2], 0.f);
                d[3] = fmaxf(acc[j][3], 0.f);
            }
        }
        __syncthreads();

        {
            float4 bb = ((const float4*)(sb2 + l2_cb))[l2_c4];
            float a0[4] = {bb.x, bb.y, bb.z, bb.w};
            float a1[4] = {bb.x, bb.y, bb.z, bb.w};
            #pragma unroll 8
            for (int f = 0; f < 256; f++) {
                float4 w = ((const float4*)(sW2 + f * H2 + l2_cb))[l2_c4];
                float z0 = sZ1[l2_r * 261 + f];
                float z1 = sZ1[(l2_r + 8) * 261 + f];
                a0[0] += z0 * w.x; a0[1] += z0 * w.y; a0[2] += z0 * w.z; a0[3] += z0 * w.w;
                a1[0] += z1 * w.x; a1[1] += z1 * w.y; a1[2] += z1 * w.z; a1[3] += z1 * w.w;
            }
            ((float4*)(sZ2 + l2_r * 132 + l2_cb))[l2_c4] =
                make_float4(fmaxf(a0[0], 0.f), fmaxf(a0[1], 0.f), fmaxf(a0[2], 0.f), fmaxf(a0[3], 0.f));
            ((float4*)(sZ2 + (l2_r + 8) * 132 + l2_cb))[l2_c4] =
                make_float4(fmaxf(a1[0], 0.f), fmaxf(a1[1], 0.f), fmaxf(a1[2], 0.f), fmaxf(a1[3], 0.f));
        }
        __syncthreads();

        if (tid < 192) {
            int r = tid / 12, p = tid % 12;
            const float* zr = sZ2 + r * 132;
            float a = sb3[p];
            #pragma unroll 16
            for (int f = 0; f < 128; f++) a += zr[f] * __ldg(&W3[f * NPRED + p]);
            int seqr = base + r;
            int bb = seqr >> 11;
            int nn = seqr & 2047;
            out[(size_t)bb * (NPRED * 2048) + p * 2048 + nn] = a;
        }
        __syncthreads();
    }
}

extern "C" void kernel_launch(void* const* d_in, const int* in_sizes, int n_in,
                              void* d_out, int out_size)
{
    const float* x     = (const float*)d_in[0];
    const float* W_in  = (const float*)d_in[1];
    const float* b_in  = (const float*)d_in[2];
    const float* W_c   = (const float*)d_in[3];
    const float* b_c   = (const float*)d_in[4];
    const float* Wq    = (const float*)d_in[5];
    const float* bq    = (const float*)d_in[6];
    const float* Wk    = (const float*)d_in[7];
    const float* bk    = (const float*)d_in[8];
    const float* Wv    = (const float*)d_in[9];
    const float* bv    = (const float*)d_in[10];
    const float* W1    = (const float*)d_in[11];
    const float* b1    = (const float*)d_in[12];
    const float* W2    = (const float*)d_in[13];
    const float* b2    = (const float*)d_in[14];
    const float* W3    = (const float*)d_in[15];
    const float* b3    = (const float*)d_in[16];

    size_t smemB = SMEM_B_FLOATS * sizeof(float);
    cudaFuncSetAttribute(kernelA, cudaFuncAttributeMaxDynamicSharedMemorySize, SMEM_A);
    cudaFuncSetAttribute(kernelB, cudaFuncAttributeMaxDynamicSharedMemorySize, (int)smemB);

    kernelA<<<152, 512, SMEM_A>>>(x, W_in, b_in, W_c, b_c, Wq, bq, Wk, bk, Wv, bv);
    kernelB<<<152, 256, smemB>>>(W1, b1, W2, b2, W3, b3, (float*)d_out);
}

// round 10
// speedup vs baseline: 1.5195x; 1.1236x over previous
#include <cuda_runtime.h>
#include <cuda_bf16.h>
#include <cstdint>

#define T 48
#define E 32
#define C0 64
#define C1 64
#define H1 256
#define H2 128
#define NPRED 12
#define SEQS (16 * 2048)
#define NQ (SEQS / 4)          // quads of 4 sequences

__device__ float g_last[SEQS * C1];
__device__ float g_M[4096];     // M = Wq . Wk^T  [j][ci] row-major
__device__ float g_WKBQ[64];    // Wk . bq
__device__ float g_WQBK[64];    // Wq . bk
__device__ float g_C0v[1];      // bq . bk

// ---- kernel A smem byte offsets (4 seqs / iter) ----
#define O_WIN_H 0        // WinT [64n][40k] bf16, stride 80B
#define O_WIN_L 5120
#define O_WC_H  10240    // WcT 3 x [64n][72k] bf16, stride 144B, dt stride 9216
#define O_WC_L  37888
#define O_X_H   65536    // x [192r][40k] bf16, stride 80B
#define O_X_L   80896
#define O_H_H   96256    // h padded [4][50][72] bf16, row stride 144B, seq stride 7200
#define O_H_L   125056
#define O_HC    153856   // hc fp32 [192][65]
#define O_LAST  203776   // fp32 [4][64]
#define O_QK    204800   // fp32 [4][64]
#define O_SC    205824   // fp32 [192]
#define O_ATTN  206592   // fp32 [4][48]
#define O_R     207360   // fp32 [4][64]
#define O_C0    208384   // fp32 [1]
#define O_WKBQ  208416   // fp32 [64]
#define O_WQBK  208672   // fp32 [64]
#define O_BIAS  208928   // fp32: bin@0 bc@64 bv@128
#define SMEM_A  209696

// ---------------- warp MMA helpers (portable PTX, plain sm_103 OK) ----------------
__device__ __forceinline__ uint32_t smem_u32(const void* p) {
    uint32_t a;
    asm("{ .reg .u64 t; cvta.to.shared.u64 t, %1; cvt.u32.u64 %0, t; }" : "=r"(a) : "l"(p));
    return a;
}
__device__ __forceinline__ void hmma(float* d, const uint32_t* a, const uint32_t* b) {
    asm volatile(
        "mma.sync.aligned.m16n8k16.row.col.f32.bf16.bf16.f32 "
        "{%0,%1,%2,%3}, {%4,%5,%6,%7}, {%8,%9}, {%0,%1,%2,%3};"
        : "+f"(d[0]), "+f"(d[1]), "+f"(d[2]), "+f"(d[3])
        : "r"(a[0]), "r"(a[1]), "r"(a[2]), "r"(a[3]), "r"(b[0]), "r"(b[1]));
}
__device__ __forceinline__ void ldA(uint32_t* f, uint32_t rowbase, int stride, int k0, int lane) {
    int g = lane >> 3;
    uint32_t addr = rowbase + (uint32_t)(((lane & 7) + ((g & 1) << 3)) * stride
                                         + (k0 + ((g >> 1) << 3)) * 2);
    asm volatile("ldmatrix.sync.aligned.m8n8.x4.shared.b16 {%0,%1,%2,%3}, [%4];"
                 : "=r"(f[0]), "=r"(f[1]), "=r"(f[2]), "=r"(f[3]) : "r"(addr));
}
__device__ __forceinline__ void ldB(uint32_t* f, uint32_t base, int stride, int cb, int k0, int lane) {
    uint32_t addr = base + (uint32_t)((cb + (lane & 7)) * stride + k0 * 2
                                      + (((lane >> 3) & 1) << 4));
    asm volatile("ldmatrix.sync.aligned.m8n8.x2.shared.b16 {%0,%1}, [%2];"
                 : "=r"(f[0]), "=r"(f[1]) : "r"(addr));
}
__device__ __forceinline__ void splitw(float a, float b, uint32_t& hw, uint32_t& lw) {
    __nv_bfloat162 H = __floats2bfloat162_rn(a, b);
    float2 F = __bfloat1622float2(H);
    __nv_bfloat162 L = __floats2bfloat162_rn(a - F.x, b - F.y);
    hw = *reinterpret_cast<uint32_t*>(&H);
    lw = *reinterpret_cast<uint32_t*>(&L);
}

// ---------------- init kernel: fold attention weights ----------------
__global__ void kernelM(const float* __restrict__ Wq, const float* __restrict__ bq,
                        const float* __restrict__ Wk, const float* __restrict__ bk)
{
    int idx = blockIdx.x * 256 + threadIdx.x;
    if (idx < 4096) {
        int j = idx >> 6, ci = idx & 63;
        float a = 0.f;
        #pragma unroll 8
        for (int co = 0; co < 64; co++) a += Wq[j * 64 + co] * Wk[ci * 64 + co];
        g_M[idx] = a;
    }
    if (blockIdx.x == 0) {
        int t = threadIdx.x;
        if (t < 64) {
            float a = 0.f, b = 0.f;
            #pragma unroll 8
            for (int co = 0; co < 64; co++) {
                a += Wk[t * 64 + co] * bq[co];
                b += Wq[t * 64 + co] * bk[co];
            }
            g_WKBQ[t] = a;
            g_WQBK[t] = b;
        }
        if (t == 64) {
            float c = 0.f;
            #pragma unroll 8
            for (int co = 0; co < 64; co++) c += bq[co] * bk[co];
            g_C0v[0] = c;
        }
    }
}

// ---------------- Kernel A: rotated pipeline, 4 seqs/iter ----------------
__global__ void __launch_bounds__(256, 1)
kernelA(const float* __restrict__ x,
        const float* __restrict__ Win, const float* __restrict__ bin,
        const float* __restrict__ Wc,  const float* __restrict__ bc,
        const float* __restrict__ Wv,  const float* __restrict__ bv)
{
    extern __shared__ char smc[];
    const uint32_t smb = smem_u32(smc);
    const int tid  = threadIdx.x;
    const int wid  = tid >> 5;
    const int lane = tid & 31;
    const int cbase = wid * 8;

    float* sBias = (float*)(smc + O_BIAS);
    float* sLast = (float*)(smc + O_LAST);
    float* sQK   = (float*)(smc + O_QK);
    float* sSC   = (float*)(smc + O_SC);
    float* sAttn = (float*)(smc + O_ATTN);
    float* sR    = (float*)(smc + O_R);
    float* sC0   = (float*)(smc + O_C0);
    float* sWKBQ = (float*)(smc + O_WKBQ);
    float* sWQBK = (float*)(smc + O_WQBK);
    float* sHC   = (float*)(smc + O_HC);

    // ---- stage weights ----
    for (int i = tid; i < 2048; i += 256) {
        int e = i >> 6, c = i & 63;
        float w = Win[i];
        __nv_bfloat16 h = __float2bfloat16(w);
        *(__nv_bfloat16*)(smc + O_WIN_H + c * 80 + e * 2) = h;
        *(__nv_bfloat16*)(smc + O_WIN_L + c * 80 + e * 2) =
            __float2bfloat16(w - __bfloat162float(h));
    }
    for (int i = tid; i < 12288; i += 256) {
        int dt = i >> 12, r = i & 4095, ci = r >> 6, co = r & 63;
        float w = Wc[i];
        __nv_bfloat16 h = __float2bfloat16(w);
        uint32_t o = dt * 9216 + co * 144 + ci * 2;
        *(__nv_bfloat16*)(smc + O_WC_H + o) = h;
        *(__nv_bfloat16*)(smc + O_WC_L + o) = __float2bfloat16(w - __bfloat162float(h));
    }
    if (tid < 64) {
        sWKBQ[tid] = g_WKBQ[tid];
        sWQBK[tid] = g_WQBK[tid];
        sBias[tid]       = bin[tid];
        sBias[64 + tid]  = bc[tid];
        sBias[128 + tid] = bv[tid];
    }
    if (tid == 128) sC0[0] = g_C0v[0];
    // zero padded-h (rows 0/49 of each seq must stay zero)
    for (int i = tid; i < 14400; i += 256) ((uint32_t*)(smc + O_H_H))[i] = 0;
    __syncthreads();

    // ---- prologue: stage x(quad0), GEMM1(quad0) -> h ----
    {
        const float4* xg = (const float4*)(x + (size_t)blockIdx.x * 4 * (T * E));
        for (int i = tid; i < 1536; i += 256) {
            float4 v = xg[i];
            int row = i >> 3, e4 = i & 7;
            uint32_t o = (uint32_t)(row * 80 + e4 * 8);
            uint32_t h0, l0, h1, l1;
            splitw(v.x, v.y, h0, l0);
            splitw(v.z, v.w, h1, l1);
            *(uint32_t*)(smc + O_X_H + o)     = h0;
            *(uint32_t*)(smc + O_X_H + o + 4) = h1;
            *(uint32_t*)(smc + O_X_L + o)     = l0;
            *(uint32_t*)(smc + O_X_L + o + 4) = l1;
        }
    }
    __syncthreads();
    {
        float acc[12][4] = {};
        #pragma unroll
        for (int k = 0; k < 2; k++) {
            int k0 = k * 16;
            uint32_t bh[2], bl[2];
            ldB(bh, smb + O_WIN_H, 80, cbase, k0, lane);
            ldB(bl, smb + O_WIN_L, 80, cbase, k0, lane);
            #pragma unroll
            for (int mt = 0; mt < 12; mt++) {
                uint32_t ah[4], al[4];
                ldA(ah, smb + O_X_H + mt * 16 * 80, 80, k0, lane);
                ldA(al, smb + O_X_L + mt * 16 * 80, 80, k0, lane);
                hmma(acc[mt], ah, bh);
                hmma(acc[mt], ah, bl);
                hmma(acc[mt], al, bh);
            }
        }
        int c = cbase + (lane & 3) * 2;
        float b0 = sBias[c], b1 = sBias[c + 1];
        #pragma unroll
        for (int mt = 0; mt < 12; mt++) {
            int s = mt / 3, j = mt % 3;
            int t0 = j * 16 + (lane >> 2), t1 = t0 + 8;
            uint32_t h0, l0, h1, l1;
            splitw(acc[mt][0] + b0, acc[mt][1] + b1, h0, l0);
            splitw(acc[mt][2] + b0, acc[mt][3] + b1, h1, l1);
            uint32_t o0 = (uint32_t)(s * 7200 + (t0 + 1) * 144 + c * 2);
            uint32_t o1 = (uint32_t)(s * 7200 + (t1 + 1) * 144 + c * 2);
            *(uint32_t*)(smc + O_H_H + o0) = h0;
            *(uint32_t*)(smc + O_H_L + o0) = l0;
            *(uint32_t*)(smc + O_H_H + o1) = h1;
            *(uint32_t*)(smc + O_H_L + o1) = l1;
        }
    }
    __syncthreads();

    // ---- main loop: [GEMM2 | tail + GEMM1-next] ----
    for (int quad = blockIdx.x; quad < NQ; quad += gridDim.x) {
        const int seq0 = quad * 4;
        const int nquad = quad + gridDim.x;
        const bool hasnext = nquad < NQ;

        // prefetch next quad's x into registers (hidden under GEMM2)
        float4 nx[6];
        if (hasnext) {
            const float4* xg = (const float4*)(x + (size_t)nquad * 4 * (T * E));
            #pragma unroll
            for (int j = 0; j < 6; j++) nx[j] = xg[tid + j * 256];
        }

        // ---- GEMM2: hc = relu(conv(h) + bc), fp32 [192][65] ----
        {
            float acc[12][4] = {};
            #pragma unroll
            for (int dt = 0; dt < 3; dt++) {
                #pragma unroll
                for (int k = 0; k < 4; k++) {
                    int k0 = k * 16;
                    uint32_t bh[2], bl[2];
                    ldB(bh, smb + O_WC_H + dt * 9216, 144, cbase, k0, lane);
                    ldB(bl, smb + O_WC_L + dt * 9216, 144, cbase, k0, lane);
                    #pragma unroll
                    for (int mt = 0; mt < 12; mt++) {
                        int s = mt / 3, j = mt % 3;
                        uint32_t rb = (uint32_t)(s * 7200 + (j * 16 + dt) * 144);
                        uint32_t ah[4], al[4];
                        ldA(ah, smb + O_H_H + rb, 144, k0, lane);
                        ldA(al, smb + O_H_L + rb, 144, k0, lane);
                        hmma(acc[mt], ah, bh);
                        hmma(acc[mt], ah, bl);
                        hmma(acc[mt], al, bh);
                    }
                }
            }
            int c = cbase + (lane & 3) * 2;
            float b0 = sBias[64 + c], b1 = sBias[64 + c + 1];
            #pragma unroll
            for (int mt = 0; mt < 12; mt++) {
                int s = mt / 3, j = mt % 3;
                int t0 = j * 16 + (lane >> 2), t1 = t0 + 8;
                int g0 = s * 48 + t0, g1 = s * 48 + t1;
                float v0 = fmaxf(acc[mt][0] + b0, 0.f), v1 = fmaxf(acc[mt][1] + b1, 0.f);
                float v2 = fmaxf(acc[mt][2] + b0, 0.f), v3 = fmaxf(acc[mt][3] + b1, 0.f);
                sHC[g0 * 65 + c]     = v0;
                sHC[g0 * 65 + c + 1] = v1;
                sHC[g1 * 65 + c]     = v2;
                sHC[g1 * 65 + c + 1] = v3;
                if (t1 == 47) {
                    sLast[s * 64 + c]     = v2;
                    sLast[s * 64 + c + 1] = v3;
                }
            }
        }

        // park prefetched x in smem (x-cur dead since previous GEMM1)
        if (hasnext) {
            #pragma unroll
            for (int j = 0; j < 6; j++) {
                float4 v = nx[j];
                int idx = tid + j * 256;
                int row = idx >> 3, e4 = idx & 7;
                uint32_t o = (uint32_t)(row * 80 + e4 * 8);
                uint32_t h0, l0, h1, l1;
                splitw(v.x, v.y, h0, l0);
                splitw(v.z, v.w, h1, l1);
                *(uint32_t*)(smc + O_X_H + o)     = h0;
                *(uint32_t*)(smc + O_X_H + o + 4) = h1;
                *(uint32_t*)(smc + O_X_L + o)     = l0;
                *(uint32_t*)(smc + O_X_L + o + 4) = l1;
            }
        }
        __syncthreads();   // hc, sLast, x-next visible

        // ---- GEMM1(next quad): compute only; store after the tail ----
        float acc1[12][4] = {};
        if (hasnext) {
            #pragma unroll
            for (int k = 0; k < 2; k++) {
                int k0 = k * 16;
                uint32_t bh[2], bl[2];
                ldB(bh, smb + O_WIN_H, 80, cbase, k0, lane);
                ldB(bl, smb + O_WIN_L, 80, cbase, k0, lane);
                #pragma unroll
                for (int mt = 0; mt < 12; mt++) {
                    uint32_t ah[4], al[4];
                    ldA(ah, smb + O_X_H + mt * 16 * 80, 80, k0, lane);
                    ldA(al, smb + O_X_L + mt * 16 * 80, 80, k0, lane);
                    hmma(acc1[mt], ah, bh);
                    hmma(acc1[mt], ah, bl);
                    hmma(acc1[mt], al, bh);
                }
            }
        }

        // ---- qk = M^T hc_last + wkbq (per-thread 64-MAC, M via L1) ----
        {
            int s = tid >> 6, c = tid & 63;
            const float* hl = sLast + s * 64;
            float a = sWKBQ[c];
            #pragma unroll 8
            for (int j = 0; j < 64; j++) a += hl[j] * __ldg(&g_M[j * 64 + c]);
            sQK[s * 64 + c] = a;
        }
        __syncthreads();

        // ---- raw scores sc[row] = <qk[s], hc[row]> ----
        if (tid < 192) {
            int row = tid, s = row / 48;
            const float* qk = sQK + s * 64;
            const float* hr = sHC + row * 65;
            float p = 0.f;
            #pragma unroll 8
            for (int j = 0; j < 64; j++) p += qk[j] * hr[j];
            sSC[row] = p;
        }
        __syncthreads();

        // ---- softmax over 48 per seq (warp s), qb folded inline ----
        if (wid < 4) {
            const float* hl = sLast + wid * 64;
            float qb = hl[lane] * sWQBK[lane] + hl[lane + 32] * sWQBK[lane + 32];
            #pragma unroll
            for (int o = 16; o > 0; o >>= 1) qb += __shfl_xor_sync(0xffffffffu, qb, o);
            qb += sC0[0];
            int base = wid * 48;
            float a  = (sSC[base + lane] + qb) * 0.125f;
            float b2 = (lane < 16) ? (sSC[base + 32 + lane] + qb) * 0.125f : -1e30f;
            float m = fmaxf(a, b2);
            #pragma unroll
            for (int o = 16; o > 0; o >>= 1) m = fmaxf(m, __shfl_xor_sync(0xffffffffu, m, o));
            float ea = __expf(a - m);
            float eb = (lane < 16) ? __expf(b2 - m) : 0.f;
            float sden = ea + eb;
            #pragma unroll
            for (int o = 16; o > 0; o >>= 1) sden += __shfl_xor_sync(0xffffffffu, sden, o);
            float inv = 1.f / sden;
            sAttn[base + lane] = ea * inv;
            if (lane < 16) sAttn[base + 32 + lane] = eb * inv;
        }
        __syncthreads();

        // ---- r = attn^T . hc ----
        {
            int s = tid >> 6, c = tid & 63;
            const float* at = sAttn + s * 48;
            const float* hb = sHC + s * 48 * 65 + c;
            float a = 0.f;
            #pragma unroll
            for (int t = 0; t < 48; t++) a += at[t] * hb[t * 65];
            sR[s * 64 + c] = a;
        }
        __syncthreads();

        // ---- ctx = r @ Wv + bv -> g_last (Wv via L1) ----
        {
            int s = tid >> 6, co = tid & 63;
            const float* r = sR + s * 64;
            float a = sBias[128 + co];
            #pragma unroll 8
            for (int ci = 0; ci < 64; ci++) a += r[ci] * __ldg(&Wv[ci * 64 + co]);
            g_last[(size_t)(seq0 + s) * 64 + co] = a;
        }

        // ---- ep1(next quad): + bin, split, store into padded h ----
        if (hasnext) {
            int c = cbase + (lane & 3) * 2;
            float b0 = sBias[c], b1 = sBias[c + 1];
            #pragma unroll
            for (int mt = 0; mt < 12; mt++) {
                int s = mt / 3, j = mt % 3;
                int t0 = j * 16 + (lane >> 2), t1 = t0 + 8;
                uint32_t h0, l0, h1, l1;
                splitw(acc1[mt][0] + b0, acc1[mt][1] + b1, h0, l0);
                splitw(acc1[mt][2] + b0, acc1[mt][3] + b1, h1, l1);
                uint32_t o0 = (uint32_t)(s * 7200 + (t0 + 1) * 144 + c * 2);
                uint32_t o1 = (uint32_t)(s * 7200 + (t1 + 1) * 144 + c * 2);
                *(uint32_t*)(smc + O_H_H + o0) = h0;
                *(uint32_t*)(smc + O_H_L + o0) = l0;
                *(uint32_t*)(smc + O_H_H + o1) = h1;
                *(uint32_t*)(smc + O_H_L + o1) = l1;
            }
        }
        __syncthreads();
    }
}

// ---------------- Kernel B: MLP (proven version; clock canary) ----------------
#define SMEM_B_FLOATS 56880

__global__ void __launch_bounds__(256, 1)
kernelB(const float* __restrict__ W1, const float* __restrict__ b1,
        const float* __restrict__ W2, const float* __restrict__ b2,
        const float* __restrict__ W3, const float* __restrict__ b3,
        float* __restrict__ out)
{
    extern __shared__ float sm[];
    float* sW1 = sm;
    float* sW2 = sm + 16384;
    float* sb1 = sm + 49152;
    float* sb2 = sm + 49408;
    float* sb3 = sm + 49536;
    float* sIn = sm + 49552;   // [16][65]
    float* sZ1 = sm + 50592;   // [16][261]
    float* sZ2 = sm + 54768;   // [16][132]

    const int tid  = threadIdx.x;
    const int wid  = tid >> 5;
    const int lane = tid & 31;

    for (int i = tid; i < 16384; i += 256) sW1[i] = W1[i];
    for (int i = tid; i < 32768; i += 256) sW2[i] = W2[i];
    if (tid < 256) sb1[tid] = b1[tid];
    if (tid < 128) sb2[tid] = b2[tid];
    if (tid < 12)  sb3[tid] = b3[tid];
    __syncthreads();

    const int l1_c4 = lane & 7;
    const int l1_r  = lane >> 3;
    const int l1_cb = wid * 32;
    const int l2_c4 = lane & 3;
    const int l2_r  = lane >> 2;
    const int l2_cb = wid * 16;

    for (int base = blockIdx.x * 16; base < SEQS; base += gridDim.x * 16) {
        {
            float4 v = ((const float4*)(g_last + (size_t)base * C1))[tid];
            int row = tid >> 4, e4 = tid & 15;
            float* d = sIn + row * 65 + e4 * 4;
            d[0] = v.x; d[1] = v.y; d[2] = v.z; d[3] = v.w;
        }
        __syncthreads();

        {
            float4 bb = ((const float4*)(sb1 + l1_cb))[l1_c4];
            float acc[4][4];
            #pragma unroll
            for (int j = 0; j < 4; j++) {
                acc[j][0] = bb.x; acc[j][1] = bb.y; acc[j][2] = bb.z; acc[j][3] = bb.w;
            }
            #pragma unroll 8
            for (int f = 0; f < 64; f++) {
                float4 w = ((const float4*)(sW1 + f * H1 + l1_cb))[l1_c4];
                float a0 = sIn[l1_r * 65 + f];
                float a1 = sIn[(l1_r + 4) * 65 + f];
                float a2 = sIn[(l1_r + 8) * 65 + f];
                float a3 = sIn[(l1_r + 12) * 65 + f];
                acc[0][0] += a0 * w.x; acc[0][1] += a0 * w.y; acc[0][2] += a0 * w.z; acc[0][3] += a0 * w.w;
                acc[1][0] += a1 * w.x; acc[1][1] += a1 * w.y; acc[1][2] += a1 * w.z; acc[1][3] += a1 * w.w;
                acc[2][0] += a2 * w.x; acc[2][1] += a2 * w.y; acc[2][2] += a2 * w.z; acc[2][3] += a2 * w.w;
                acc[3][0] += a3 * w.x; acc[3][1] += a3 * w.y; acc[3][2] += a3 * w.z; acc[3][3] += a3 * w.w;
            }
            #pragma unroll
            for (int j = 0; j < 4; j++) {
                float* d = sZ1 + (l1_r + 4 * j) * 261 + l1_cb + l1_c4 * 4;
                d[0] = fmaxf(acc[j][0], 0.f);
                d[1] = fmaxf(acc[j][1], 0.f);
                d[2] = fmaxf(acc[j][2], 0.f);
                d[3] = fmaxf(acc[j][3], 0.f);
            }
        }
        __syncthreads();

        {
            float4 bb = ((const float4*)(sb2 + l2_cb))[l2_c4];
            float a0[4] = {bb.x, bb.y, bb.z, bb.w};
            float a1[4] = {bb.x, bb.y, bb.z, bb.w};
            #pragma unroll 8
            for (int f = 0; f < 256; f++) {
                float4 w = ((const float4*)(sW2 + f * H2 + l2_cb))[l2_c4];
                float z0 = sZ1[l2_r * 261 + f];
                float z1 = sZ1[(l2_r + 8) * 261 + f];
                a0[0] += z0 * w.x; a0[1] += z0 * w.y; a0[2] += z0 * w.z; a0[3] += z0 * w.w;
                a1[0] += z1 * w.x; a1[1] += z1 * w.y; a1[2] += z1 * w.z; a1[3] += z1 * w.w;
            }
            ((float4*)(sZ2 + l2_r * 132 + l2_cb))[l2_c4] =
                make_float4(fmaxf(a0[0], 0.f), fmaxf(a0[1], 0.f), fmaxf(a0[2], 0.f), fmaxf(a0[3], 0.f));
            ((float4*)(sZ2 + (l2_r + 8) * 132 + l2_cb))[l2_c4] =
                make_float4(fmaxf(a1[0], 0.f), fmaxf(a1[1], 0.f), fmaxf(a1[2], 0.f), fmaxf(a1[3], 0.f));
        }
        __syncthreads();

        if (tid < 192) {
            int r = tid / 12, p = tid % 12;
            const float* zr = sZ2 + r * 132;
            float a = sb3[p];
            #pragma unroll 16
            for (int f = 0; f < 128; f++) a += zr[f] * __ldg(&W3[f * NPRED + p]);
            int seqr = base + r;
            int bb = seqr >> 11;
            int nn = seqr & 2047;
            out[(size_t)bb * (NPRED * 2048) + p * 2048 + nn] = a;
        }
        __syncthreads();
    }
}

extern "C" void kernel_launch(void* const* d_in, const int* in_sizes, int n_in,
                              void* d_out, int out_size)
{
    const float* x     = (const float*)d_in[0];
    const float* W_in  = (const float*)d_in[1];
    const float* b_in  = (const float*)d_in[2];
    const float* W_c   = (const float*)d_in[3];
    const float* b_c   = (const float*)d_in[4];
    const float* Wq    = (const float*)d_in[5];
    const float* bq    = (const float*)d_in[6];
    const float* Wk    = (const float*)d_in[7];
    const float* bk    = (const float*)d_in[8];
    const float* Wv    = (const float*)d_in[9];
    const float* bv    = (const float*)d_in[10];
    const float* W1    = (const float*)d_in[11];
    const float* b1    = (const float*)d_in[12];
    const float* W2    = (const float*)d_in[13];
    const float* b2    = (const float*)d_in[14];
    const float* W3    = (const float*)d_in[15];
    const float* b3    = (const float*)d_in[16];

    size_t smemB = SMEM_B_FLOATS * sizeof(float);
    cudaFuncSetAttribute(kernelA, cudaFuncAttributeMaxDynamicSharedMemorySize, SMEM_A);
    cudaFuncSetAttribute(kernelB, cudaFuncAttributeMaxDynamicSharedMemorySize, (int)smemB);

    kernelM<<<16, 256>>>(Wq, bq, Wk, bk);
    kernelA<<<152, 256, SMEM_A>>>(x, W_in, b_in, W_c, b_c, Wv, bv);
    kernelB<<<152, 256, smemB>>>(W1, b1, W2, b2, W3, b3, (float*)d_out);
}

// round 11
// speedup vs baseline: 1.9721x; 1.2978x over previous
#include <cuda_runtime.h>
#include <cuda_bf16.h>
#include <cstdint>

#define T 48
#define E 32
#define C0 64
#define C1 64
#define H1 256
#define H2 128
#define NPRED 12
#define SEQS (16 * 2048)
#define NQ (SEQS / 4)

__device__ float g_last[SEQS * C1];    // holds r (ctx folded into MLP weights)
__device__ float g_M[4096];            // M = Wq . Wk^T  [j][ci]
__device__ float g_W1p[64 * 256];      // W1' = Wv . W1
__device__ float g_b1p[256];           // b1' = b1 + bv . W1
__device__ float g_WKBQ[64];
__device__ float g_WQBK[64];
__device__ float g_C0v[1];

// ---- kernel A smem byte offsets (4 seqs / iter) ----
#define O_WIN_H 0        // WinT [64n][40k] bf16, stride 80B
#define O_WIN_L 5120
#define O_WC_H  10240    // WcT 3 x [64n][72k] bf16, stride 144B, dt stride 9216
#define O_WC_L  37888
#define O_X_H   65536    // x [192r][40k] bf16, stride 80B
#define O_X_L   80896
#define O_H_H   96256    // h padded [4][50][72] bf16, row stride 144B, seq stride 7200
#define O_H_L   125056
#define O_HC    153856   // hc fp32 [192][68]
#define O_LAST  206080   // fp32 [4][64]
#define O_QK    207104   // fp32 [4][64]
#define O_SC    208128   // fp32 [192]
#define O_ATTN  208896   // fp32 [4][48]
#define O_C0    209664
#define O_WKBQ  209680
#define O_WQBK  209936
#define O_BIAS  210192   // fp32: bin@0 bc@64
#define O_M     210704   // fp32 [64][65]
#define SMEM_A  227344

// ---------------- warp MMA helpers ----------------
__device__ __forceinline__ uint32_t smem_u32(const void* p) {
    uint32_t a;
    asm("{ .reg .u64 t; cvta.to.shared.u64 t, %1; cvt.u32.u64 %0, t; }" : "=r"(a) : "l"(p));
    return a;
}
__device__ __forceinline__ void hmma(float* d, const uint32_t* a, const uint32_t* b) {
    asm volatile(
        "mma.sync.aligned.m16n8k16.row.col.f32.bf16.bf16.f32 "
        "{%0,%1,%2,%3}, {%4,%5,%6,%7}, {%8,%9}, {%0,%1,%2,%3};"
        : "+f"(d[0]), "+f"(d[1]), "+f"(d[2]), "+f"(d[3])
        : "r"(a[0]), "r"(a[1]), "r"(a[2]), "r"(a[3]), "r"(b[0]), "r"(b[1]));
}
__device__ __forceinline__ void ldA(uint32_t* f, uint32_t rowbase, int stride, int k0, int lane) {
    int g = lane >> 3;
    uint32_t addr = rowbase + (uint32_t)(((lane & 7) + ((g & 1) << 3)) * stride
                                         + (k0 + ((g >> 1) << 3)) * 2);
    asm volatile("ldmatrix.sync.aligned.m8n8.x4.shared.b16 {%0,%1,%2,%3}, [%4];"
                 : "=r"(f[0]), "=r"(f[1]), "=r"(f[2]), "=r"(f[3]) : "r"(addr));
}
__device__ __forceinline__ void ldB(uint32_t* f, uint32_t base, int stride, int cb, int k0, int lane) {
    uint32_t addr = base + (uint32_t)((cb + (lane & 7)) * stride + k0 * 2
                                      + (((lane >> 3) & 1) << 4));
    asm volatile("ldmatrix.sync.aligned.m8n8.x2.shared.b16 {%0,%1}, [%2];"
                 : "=r"(f[0]), "=r"(f[1]) : "r"(addr));
}
__device__ __forceinline__ void splitw(float a, float b, uint32_t& hw, uint32_t& lw) {
    __nv_bfloat162 H = __floats2bfloat162_rn(a, b);
    float2 F = __bfloat1622float2(H);
    __nv_bfloat162 L = __floats2bfloat162_rn(a - F.x, b - F.y);
    hw = *reinterpret_cast<uint32_t*>(&H);
    lw = *reinterpret_cast<uint32_t*>(&L);
}

// ---------------- init kernel: fold attention + ctx weights ----------------
__global__ void __launch_bounds__(256)
kernelM(const float* __restrict__ Wq, const float* __restrict__ bq,
        const float* __restrict__ Wk, const float* __restrict__ bk,
        const float* __restrict__ Wv, const float* __restrict__ bv,
        const float* __restrict__ W1, const float* __restrict__ b1)
{
    int idx = blockIdx.x * 256 + threadIdx.x;
    if (idx < 4096) {                       // M = Wq . Wk^T
        int j = idx >> 6, ci = idx & 63;
        float a = 0.f;
        #pragma unroll 8
        for (int co = 0; co < 64; co++) a += Wq[j * 64 + co] * Wk[ci * 64 + co];
        g_M[idx] = a;
    } else if (idx < 4096 + 16384) {        // W1' = Wv . W1
        int o = idx - 4096;
        int ci = o >> 8, n = o & 255;
        float a = 0.f;
        #pragma unroll 8
        for (int co = 0; co < 64; co++) a += Wv[ci * 64 + co] * W1[co * 256 + n];
        g_W1p[o] = a;
    } else if (idx < 20480 + 256) {         // b1' = b1 + bv . W1
        int n = idx - 20480;
        float a = b1[n];
        #pragma unroll 8
        for (int co = 0; co < 64; co++) a += bv[co] * W1[co * 256 + n];
        g_b1p[n] = a;
    } else if (idx < 20736 + 64) {          // WKBQ, WQBK
        int t2 = idx - 20736;
        float a = 0.f, b = 0.f;
        #pragma unroll 8
        for (int co = 0; co < 64; co++) {
            a += Wk[t2 * 64 + co] * bq[co];
            b += Wq[t2 * 64 + co] * bk[co];
        }
        g_WKBQ[t2] = a;
        g_WQBK[t2] = b;
    } else if (idx == 20800) {
        float c = 0.f;
        #pragma unroll 8
        for (int co = 0; co < 64; co++) c += bq[co] * bk[co];
        g_C0v[0] = c;
    }
}

// ---------------- Kernel A: rotated pipeline, 4 seqs/iter, r-output ----------------
__global__ void __launch_bounds__(256, 1)
kernelA(const float* __restrict__ x,
        const float* __restrict__ Win, const float* __restrict__ bin,
        const float* __restrict__ Wc,  const float* __restrict__ bc)
{
    extern __shared__ char smc[];
    const uint32_t smb = smem_u32(smc);
    const int tid  = threadIdx.x;
    const int wid  = tid >> 5;
    const int lane = tid & 31;
    const int cbase = wid * 8;

    float* sBias = (float*)(smc + O_BIAS);
    float* sLast = (float*)(smc + O_LAST);
    float* sQK   = (float*)(smc + O_QK);
    float* sSC   = (float*)(smc + O_SC);
    float* sAttn = (float*)(smc + O_ATTN);
    float* sC0   = (float*)(smc + O_C0);
    float* sWKBQ = (float*)(smc + O_WKBQ);
    float* sWQBK = (float*)(smc + O_WQBK);
    float* sHC   = (float*)(smc + O_HC);
    float* sM    = (float*)(smc + O_M);      // [64][65]

    // ---- stage weights ----
    for (int i = tid; i < 2048; i += 256) {
        int e = i >> 6, c = i & 63;
        float w = Win[i];
        __nv_bfloat16 h = __float2bfloat16(w);
        *(__nv_bfloat16*)(smc + O_WIN_H + c * 80 + e * 2) = h;
        *(__nv_bfloat16*)(smc + O_WIN_L + c * 80 + e * 2) =
            __float2bfloat16(w - __bfloat162float(h));
    }
    for (int i = tid; i < 12288; i += 256) {
        int dt = i >> 12, r = i & 4095, ci = r >> 6, co = r & 63;
        float w = Wc[i];
        __nv_bfloat16 h = __float2bfloat16(w);
        uint32_t o = dt * 9216 + co * 144 + ci * 2;
        *(__nv_bfloat16*)(smc + O_WC_H + o) = h;
        *(__nv_bfloat16*)(smc + O_WC_L + o) = __float2bfloat16(w - __bfloat162float(h));
    }
    for (int i = tid; i < 4096; i += 256) {     // M -> smem, re-stride to 65
        int j = i >> 6, ci = i & 63;
        sM[j * 65 + ci] = g_M[i];
    }
    if (tid < 64) {
        sWKBQ[tid] = g_WKBQ[tid];
        sWQBK[tid] = g_WQBK[tid];
        sBias[tid]      = bin[tid];
        sBias[64 + tid] = bc[tid];
    }
    if (tid == 128) sC0[0] = g_C0v[0];
    for (int i = tid; i < 14400; i += 256) ((uint32_t*)(smc + O_H_H))[i] = 0;
    __syncthreads();

    // ---- prologue: stage x(quad0), GEMM1(quad0) -> h ----
    {
        const float4* xg = (const float4*)(x + (size_t)blockIdx.x * 4 * (T * E));
        for (int i = tid; i < 1536; i += 256) {
            float4 v = xg[i];
            int row = i >> 3, e4 = i & 7;
            uint32_t o = (uint32_t)(row * 80 + e4 * 8);
            uint32_t h0, l0, h1, l1;
            splitw(v.x, v.y, h0, l0);
            splitw(v.z, v.w, h1, l1);
            *(uint32_t*)(smc + O_X_H + o)     = h0;
            *(uint32_t*)(smc + O_X_H + o + 4) = h1;
            *(uint32_t*)(smc + O_X_L + o)     = l0;
            *(uint32_t*)(smc + O_X_L + o + 4) = l1;
        }
    }
    __syncthreads();
    {
        float acc[12][4] = {};
        #pragma unroll
        for (int k = 0; k < 2; k++) {
            int k0 = k * 16;
            uint32_t bh[2], bl[2];
            ldB(bh, smb + O_WIN_H, 80, cbase, k0, lane);
            ldB(bl, smb + O_WIN_L, 80, cbase, k0, lane);
            #pragma unroll
            for (int mt = 0; mt < 12; mt++) {
                uint32_t ah[4], al[4];
                ldA(ah, smb + O_X_H + mt * 16 * 80, 80, k0, lane);
                ldA(al, smb + O_X_L + mt * 16 * 80, 80, k0, lane);
                hmma(acc[mt], ah, bh);
                hmma(acc[mt], ah, bl);
                hmma(acc[mt], al, bh);
            }
        }
        int c = cbase + (lane & 3) * 2;
        float b0 = sBias[c], b1v = sBias[c + 1];
        #pragma unroll
        for (int mt = 0; mt < 12; mt++) {
            int s = mt / 3, j = mt % 3;
            int t0 = j * 16 + (lane >> 2), t1 = t0 + 8;
            uint32_t h0, l0, h1, l1;
            splitw(acc[mt][0] + b0, acc[mt][1] + b1v, h0, l0);
            splitw(acc[mt][2] + b0, acc[mt][3] + b1v, h1, l1);
            uint32_t o0 = (uint32_t)(s * 7200 + (t0 + 1) * 144 + c * 2);
            uint32_t o1 = (uint32_t)(s * 7200 + (t1 + 1) * 144 + c * 2);
            *(uint32_t*)(smc + O_H_H + o0) = h0;
            *(uint32_t*)(smc + O_H_L + o0) = l0;
            *(uint32_t*)(smc + O_H_H + o1) = h1;
            *(uint32_t*)(smc + O_H_L + o1) = l1;
        }
    }
    __syncthreads();

    // ---- main loop ----
    for (int quad = blockIdx.x; quad < NQ; quad += gridDim.x) {
        const int seq0 = quad * 4;
        const int nquad = quad + gridDim.x;
        const bool hasnext = nquad < NQ;

        float4 nx[6];
        if (hasnext) {
            const float4* xg = (const float4*)(x + (size_t)nquad * 4 * (T * E));
            #pragma unroll
            for (int j = 0; j < 6; j++) nx[j] = xg[tid + j * 256];
        }

        // ---- GEMM2: hc = relu(conv(h) + bc), fp32 [192][68] ----
        {
            float acc[12][4] = {};
            #pragma unroll
            for (int dt = 0; dt < 3; dt++) {
                #pragma unroll
                for (int k = 0; k < 4; k++) {
                    int k0 = k * 16;
                    uint32_t bh[2], bl[2];
                    ldB(bh, smb + O_WC_H + dt * 9216, 144, cbase, k0, lane);
                    ldB(bl, smb + O_WC_L + dt * 9216, 144, cbase, k0, lane);
                    #pragma unroll
                    for (int mt = 0; mt < 12; mt++) {
                        int s = mt / 3, j = mt % 3;
                        uint32_t rb = (uint32_t)(s * 7200 + (j * 16 + dt) * 144);
                        uint32_t ah[4], al[4];
                        ldA(ah, smb + O_H_H + rb, 144, k0, lane);
                        ldA(al, smb + O_H_L + rb, 144, k0, lane);
                        hmma(acc[mt], ah, bh);
                        hmma(acc[mt], ah, bl);
                        hmma(acc[mt], al, bh);
                    }
                }
            }
            int c = cbase + (lane & 3) * 2;
            float b0 = sBias[64 + c], b1v = sBias[64 + c + 1];
            #pragma unroll
            for (int mt = 0; mt < 12; mt++) {
                int s = mt / 3, j = mt % 3;
                int t0 = j * 16 + (lane >> 2), t1 = t0 + 8;
                int g0 = s * 48 + t0, g1 = s * 48 + t1;
                float v0 = fmaxf(acc[mt][0] + b0, 0.f), v1 = fmaxf(acc[mt][1] + b1v, 0.f);
                float v2 = fmaxf(acc[mt][2] + b0, 0.f), v3 = fmaxf(acc[mt][3] + b1v, 0.f);
                sHC[g0 * 68 + c]     = v0;
                sHC[g0 * 68 + c + 1] = v1;
                sHC[g1 * 68 + c]     = v2;
                sHC[g1 * 68 + c + 1] = v3;
                if (t1 == 47) {
                    sLast[s * 64 + c]     = v2;
                    sLast[s * 64 + c + 1] = v3;
                }
            }
        }

        if (hasnext) {
            #pragma unroll
            for (int j = 0; j < 6; j++) {
                float4 v = nx[j];
                int idx = tid + j * 256;
                int row = idx >> 3, e4 = idx & 7;
                uint32_t o = (uint32_t)(row * 80 + e4 * 8);
                uint32_t h0, l0, h1, l1;
                splitw(v.x, v.y, h0, l0);
                splitw(v.z, v.w, h1, l1);
                *(uint32_t*)(smc + O_X_H + o)     = h0;
                *(uint32_t*)(smc + O_X_H + o + 4) = h1;
                *(uint32_t*)(smc + O_X_L + o)     = l0;
                *(uint32_t*)(smc + O_X_L + o + 4) = l1;
            }
        }
        __syncthreads();

        // ---- GEMM1(next quad): compute only ----
        float acc1[12][4] = {};
        if (hasnext) {
            #pragma unroll
            for (int k = 0; k < 2; k++) {
                int k0 = k * 16;
                uint32_t bh[2], bl[2];
                ldB(bh, smb + O_WIN_H, 80, cbase, k0, lane);
                ldB(bl, smb + O_WIN_L, 80, cbase, k0, lane);
                #pragma unroll
                for (int mt = 0; mt < 12; mt++) {
                    uint32_t ah[4], al[4];
                    ldA(ah, smb + O_X_H + mt * 16 * 80, 80, k0, lane);
                    ldA(al, smb + O_X_L + mt * 16 * 80, 80, k0, lane);
                    hmma(acc1[mt], ah, bh);
                    hmma(acc1[mt], ah, bl);
                    hmma(acc1[mt], al, bh);
                }
            }
        }

        // ---- qk = M^T hc_last + wkbq (smem M) ----
        {
            int s = tid >> 6, c = tid & 63;
            const float* hl = sLast + s * 64;
            float a = sWKBQ[c];
            #pragma unroll 8
            for (int j = 0; j < 64; j++) a += hl[j] * sM[j * 65 + c];
            sQK[s * 64 + c] = a;
        }
        __syncthreads();

        // ---- raw scores: float4 dot over [68]-stride rows ----
        if (tid < 192) {
            int row = tid, s = row / 48;
            const float4* qk4 = (const float4*)(sQK + s * 64);
            const float4* hr4 = (const float4*)(sHC + row * 68);
            float p = 0.f;
            #pragma unroll
            for (int j = 0; j < 16; j++) {
                float4 a4 = qk4[j], b4 = hr4[j];
                p += a4.x * b4.x + a4.y * b4.y + a4.z * b4.z + a4.w * b4.w;
            }
            sSC[row] = p;
        }
        __syncthreads();

        // ---- softmax over 48 per seq (warp s), qb inline ----
        if (wid < 4) {
            const float* hl = sLast + wid * 64;
            float qb = hl[lane] * sWQBK[lane] + hl[lane + 32] * sWQBK[lane + 32];
            #pragma unroll
            for (int o = 16; o > 0; o >>= 1) qb += __shfl_xor_sync(0xffffffffu, qb, o);
            qb += sC0[0];
            int base = wid * 48;
            float a  = (sSC[base + lane] + qb) * 0.125f;
            float b2 = (lane < 16) ? (sSC[base + 32 + lane] + qb) * 0.125f : -1e30f;
            float m = fmaxf(a, b2);
            #pragma unroll
            for (int o = 16; o > 0; o >>= 1) m = fmaxf(m, __shfl_xor_sync(0xffffffffu, m, o));
            float ea = __expf(a - m);
            float eb = (lane < 16) ? __expf(b2 - m) : 0.f;
            float sden = ea + eb;
            #pragma unroll
            for (int o = 16; o > 0; o >>= 1) sden += __shfl_xor_sync(0xffffffffu, sden, o);
            float inv = 1.f / sden;
            sAttn[base + lane] = ea * inv;
            if (lane < 16) sAttn[base + 32 + lane] = eb * inv;
        }
        __syncthreads();

        // ---- r = attn^T . hc  -> g_last directly (ctx folded into MLP) ----
        {
            int s = tid >> 6, c = tid & 63;
            const float* at = sAttn + s * 48;
            const float* hb = sHC + s * 48 * 68 + c;
            float a = 0.f;
            #pragma unroll
            for (int t = 0; t < 48; t++) a += at[t] * hb[t * 68];
            g_last[(size_t)(seq0 + s) * 64 + c] = a;
        }

        // ---- ep1(next quad) ----
        if (hasnext) {
            int c = cbase + (lane & 3) * 2;
            float b0 = sBias[c], b1v = sBias[c + 1];
            #pragma unroll
            for (int mt = 0; mt < 12; mt++) {
                int s = mt / 3, j = mt % 3;
                int t0 = j * 16 + (lane >> 2), t1 = t0 + 8;
                uint32_t h0, l0, h1, l1;
                splitw(acc1[mt][0] + b0, acc1[mt][1] + b1v, h0, l0);
                splitw(acc1[mt][2] + b0, acc1[mt][3] + b1v, h1, l1);
                uint32_t o0 = (uint32_t)(s * 7200 + (t0 + 1) * 144 + c * 2);
                uint32_t o1 = (uint32_t)(s * 7200 + (t1 + 1) * 144 + c * 2);
                *(uint32_t*)(smc + O_H_H + o0) = h0;
                *(uint32_t*)(smc + O_H_L + o0) = l0;
                *(uint32_t*)(smc + O_H_H + o1) = h1;
                *(uint32_t*)(smc + O_H_L + o1) = l1;
            }
        }
        __syncthreads();
    }
}

// ---------------- Kernel B: MLP (W1', b1' from globals; clock canary) ----------------
#define SMEM_B_FLOATS 56880

__global__ void __launch_bounds__(256, 1)
kernelB(const float* __restrict__ W2, const float* __restrict__ b2,
        const float* __restrict__ W3, const float* __restrict__ b3,
        float* __restrict__ out)
{
    extern __shared__ float sm[];
    float* sW1 = sm;
    float* sW2 = sm + 16384;
    float* sb1 = sm + 49152;
    float* sb2 = sm + 49408;
    float* sb3 = sm + 49536;
    float* sIn = sm + 49552;   // [16][65]
    float* sZ1 = sm + 50592;   // [16][261]
    float* sZ2 = sm + 54768;   // [16][132]

    const int tid  = threadIdx.x;
    const int wid  = tid >> 5;
    const int lane = tid & 31;

    for (int i = tid; i < 16384; i += 256) sW1[i] = g_W1p[i];
    for (int i = tid; i < 32768; i += 256) sW2[i] = W2[i];
    if (tid < 256) sb1[tid] = g_b1p[tid];
    if (tid < 128) sb2[tid] = b2[tid];
    if (tid < 12)  sb3[tid] = b3[tid];
    __syncthreads();

    const int l1_c4 = lane & 7;
    const int l1_r  = lane >> 3;
    const int l1_cb = wid * 32;
    const int l2_c4 = lane & 3;
    const int l2_r  = lane >> 2;
    const int l2_cb = wid * 16;

    for (int base = blockIdx.x * 16; base < SEQS; base += gridDim.x * 16) {
        {
            float4 v = ((const float4*)(g_last + (size_t)base * C1))[tid];
            int row = tid >> 4, e4 = tid & 15;
            float* d = sIn + row * 65 + e4 * 4;
            d[0] = v.x; d[1] = v.y; d[2] = v.z; d[3] = v.w;
        }
        __syncthreads();

        {
            float4 bb = ((const float4*)(sb1 + l1_cb))[l1_c4];
            float acc[4][4];
            #pragma unroll
            for (int j = 0; j < 4; j++) {
                acc[j][0] = bb.x; acc[j][1] = bb.y; acc[j][2] = bb.z; acc[j][3] = bb.w;
            }
            #pragma unroll 8
            for (int f = 0; f < 64; f++) {
                float4 w = ((const float4*)(sW1 + f * H1 + l1_cb))[l1_c4];
                float a0 = sIn[l1_r * 65 + f];
                float a1 = sIn[(l1_r + 4) * 65 + f];
                float a2 = sIn[(l1_r + 8) * 65 + f];
                float a3 = sIn[(l1_r + 12) * 65 + f];
                acc[0][0] += a0 * w.x; acc[0][1] += a0 * w.y; acc[0][2] += a0 * w.z; acc[0][3] += a0 * w.w;
                acc[1][0] += a1 * w.x; acc[1][1] += a1 * w.y; acc[1][2] += a1 * w.z; acc[1][3] += a1 * w.w;
                acc[2][0] += a2 * w.x; acc[2][1] += a2 * w.y; acc[2][2] += a2 * w.z; acc[2][3] += a2 * w.w;
                acc[3][0] += a3 * w.x; acc[3][1] += a3 * w.y; acc[3][2] += a3 * w.z; acc[3][3] += a3 * w.w;
            }
            #pragma unroll
            for (int j = 0; j < 4; j++) {
                float* d = sZ1 + (l1_r + 4 * j) * 261 + l1_cb + l1_c4 * 4;
                d[0] = fmaxf(acc[j][0], 0.f);
                d[1] = fmaxf(acc[j][1], 0.f);
                d[2] = fmaxf(acc[j][2], 0.f);
                d[3] = fmaxf(acc[j][3], 0.f);
            }
        }
        __syncthreads();

        {
            float4 bb = ((const float4*)(sb2 + l2_cb))[l2_c4];
            float a0[4] = {bb.x, bb.y, bb.z, bb.w};
            float a1[4] = {bb.x, bb.y, bb.z, bb.w};
            #pragma unroll 8
            for (int f = 0; f < 256; f++) {
                float4 w = ((const float4*)(sW2 + f * H2 + l2_cb))[l2_c4];
                float z0 = sZ1[l2_r * 261 + f];
                float z1 = sZ1[(l2_r + 8) * 261 + f];
                a0[0] += z0 * w.x; a0[1] += z0 * w.y; a0[2] += z0 * w.z; a0[3] += z0 * w.w;
                a1[0] += z1 * w.x; a1[1] += z1 * w.y; a1[2] += z1 * w.z; a1[3] += z1 * w.w;
            }
            ((float4*)(sZ2 + l2_r * 132 + l2_cb))[l2_c4] =
                make_float4(fmaxf(a0[0], 0.f), fmaxf(a0[1], 0.f), fmaxf(a0[2], 0.f), fmaxf(a0[3], 0.f));
            ((float4*)(sZ2 + (l2_r + 8) * 132 + l2_cb))[l2_c4] =
                make_float4(fmaxf(a1[0], 0.f), fmaxf(a1[1], 0.f), fmaxf(a1[2], 0.f), fmaxf(a1[3], 0.f));
        }
        __syncthreads();

        if (tid < 192) {
            int r = tid / 12, p = tid % 12;
            const float* zr = sZ2 + r * 132;
            float a = sb3[p];
            #pragma unroll 16
            for (int f = 0; f < 128; f++) a += zr[f] * __ldg(&W3[f * NPRED + p]);
            int seqr = base + r;
            int bb = seqr >> 11;
            int nn = seqr & 2047;
            out[(size_t)bb * (NPRED * 2048) + p * 2048 + nn] = a;
        }
        __syncthreads();
    }
}

extern "C" void kernel_launch(void* const* d_in, const int* in_sizes, int n_in,
                              void* d_out, int out_size)
{
    const float* x     = (const float*)d_in[0];
    const float* W_in  = (const float*)d_in[1];
    const float* b_in  = (const float*)d_in[2];
    const float* W_c   = (const float*)d_in[3];
    const float* b_c   = (const float*)d_in[4];
    const float* Wq    = (const float*)d_in[5];
    const float* bq    = (const float*)d_in[6];
    const float* Wk    = (const float*)d_in[7];
    const float* bk    = (const float*)d_in[8];
    const float* Wv    = (const float*)d_in[9];
    const float* bv    = (const float*)d_in[10];
    const float* W1    = (const float*)d_in[11];
    const float* b1    = (const float*)d_in[12];
    const float* W2    = (const float*)d_in[13];
    const float* b2    = (const float*)d_in[14];
    const float* W3    = (const float*)d_in[15];
    const float* b3    = (const float*)d_in[16];

    size_t smemB = SMEM_B_FLOATS * sizeof(float);
    cudaFuncSetAttribute(kernelA, cudaFuncAttributeMaxDynamicSharedMemorySize, SMEM_A);
    cudaFuncSetAttribute(kernelB, cudaFuncAttributeMaxDynamicSharedMemorySize, (int)smemB);

    kernelM<<<82, 256>>>(Wq, bq, Wk, bk, Wv, bv, W1, b1);
    kernelA<<<152, 256, SMEM_A>>>(x, W_in, b_in, W_c, b_c);
    kernelB<<<152, 256, smemB>>>(W2, b2, W3, b3, (float*)d_out);
}